// round 10
// baseline (speedup 1.0000x reference)
#include <cuda_runtime.h>
#include <math.h>

#define N_NODES 32768
#define E_EDGES 524288
#define F_CH    128
#define Z_SP    10

typedef unsigned long long ull;

// ---------------- scratch (static device globals; no allocation) -------------
__device__ float g_hs  [N_NODES * F_CH];
__device__ float g_hv  [N_NODES * F_CH * 3];
__device__ float g_self[N_NODES * F_CH];
__device__ float g_h3t [64 * E_EDGES];        // transposed [k][e]
__device__ float g_aggs[N_NODES * F_CH];
__device__ float g_aggv[N_NODES * F_CH * 3];
__device__ float g_xs  [N_NODES * F_CH];
__device__ float g_xv  [N_NODES * F_CH * 3];
__device__ float g_tmp [N_NODES * F_CH];
__device__ int   g_cnt [Z_SP];
__device__ int   g_list[Z_SP * N_NODES];

#define INV_SQRT128  0.08838834764831845f
#define INV_SQRT1280 0.027950849718747372f
#define INV_SQRT8    0.35355339059327373f
#define INV_SQRT3F   0.5773502691896258f
#define INV_SQRT2F   0.7071067811865476f
#define INV_SQRT10F  0.31622776601683794f
#define K_MIX        0.015625f   /* inv(w4)=1/8 times EPS=1/8 */

__device__ __forceinline__ float silu_f(float x) {
    return x * (1.0f / (1.0f + __expf(-x)));
}
__device__ __forceinline__ ull pack2(float x, float y) {
    ull r; asm("mov.b64 %0, {%1, %2};" : "=l"(r) : "f"(x), "f"(y)); return r;
}
__device__ __forceinline__ float2 unpack2(ull v) {
    float2 r; asm("mov.b64 {%0, %1}, %2;" : "=f"(r.x), "=f"(r.y) : "l"(v)); return r;
}
__device__ __forceinline__ void fma2(ull &d, ull a, ull b) {
    asm("fma.rn.f32x2 %0, %1, %2, %0;" : "+l"(d) : "l"(a), "l"(b));
}
// vectored global float2 reduction (sm_90+), fire-and-forget
__device__ __forceinline__ void red2(float* p, float a, float b) {
    asm volatile("red.global.add.v2.f32 [%0], {%1, %2};"
                 :: "l"(p), "f"(a), "f"(b) : "memory");
}

// ---------------- species bucketing ------------------------------------------
__global__ void k_species_list(const int* __restrict__ species) {
    int n = blockIdx.x * 256 + threadIdx.x;
    if (n < N_NODES) {
        int z = species[n];
        int pos = atomicAdd(&g_cnt[z], 1);
        g_list[z * N_NODES + pos] = n;
    }
}

// ---------------- scalar-channel GEMM [64-row tile,128]@[128,128] ------------
// 256 thr: g = tid&127, h = tid>>7 owns rows [32h,32h+32) as 16 packed pairs.
// X staged transposed Xs[f][r] so one LDS.64 = a row-pair (warp-broadcast).
__global__ void k_gemm_s(const float* __restrict__ X, const float* __restrict__ W,
                         float* __restrict__ O, const float* __restrict__ Add,
                         float scale) {
    extern __shared__ float sm[];
    float* Ws = sm;           // 128*128
    float* Xs = sm + 16384;   // 128 * 66 (transposed, padded)
    int tid = threadIdx.x;
    for (int i = tid; i < 16384; i += 256) Ws[i] = W[i];
    int base = blockIdx.x * 64;
    const float* Xrow = X + (size_t)base * 128;
    for (int i = tid; i < 8192; i += 256) {
        int r = i >> 7, f = i & 127;
        Xs[f * 66 + r] = Xrow[i];
    }
    __syncthreads();
    int g = tid & 127;
    int h = tid >> 7;
    const ull* Xp = (const ull*)Xs;   // pair idx = f*33 + j  (rows 2j,2j+1)
    ull acc[16];
    #pragma unroll
    for (int j = 0; j < 16; j++) acc[j] = 0ull;
    #pragma unroll 4
    for (int f = 0; f < 128; f++) {
        float w = Ws[f * 128 + g];
        ull wd = pack2(w, w);
        int pb = f * 33 + h * 16;
        #pragma unroll
        for (int j = 0; j < 16; j++) fma2(acc[j], Xp[pb + j], wd);
    }
    #pragma unroll
    for (int j = 0; j < 16; j++) {
        float2 v = unpack2(acc[j]);
        int n0 = base + h * 32 + 2 * j;
        float a = v.x * scale, b = v.y * scale;
        if (Add) {
            a += Add[(size_t)n0 * 128 + g];
            b += Add[(size_t)(n0 + 1) * 128 + g];
        }
        O[(size_t)n0 * 128 + g]       = a;
        O[(size_t)(n0 + 1) * 128 + g] = b;
    }
}

// ---------------- species-indexed skip GEMM (same scheme, gathered rows) -----
__global__ void k_gemm_sc(const float* __restrict__ X, const float* __restrict__ w_skip,
                          float* __restrict__ Self) {
    extern __shared__ float sm[];
    float* Ws = sm;
    float* Xs = sm + 16384;
    __shared__ int lsts[64];
    int z = blockIdx.y;
    int cnt = g_cnt[z];
    int t0 = blockIdx.x * 64;
    if (t0 >= cnt) return;
    int tid = threadIdx.x;
    const float* W = w_skip + z * 16384;
    for (int i = tid; i < 16384; i += 256) Ws[i] = W[i];
    int rows = cnt - t0; if (rows > 64) rows = 64;
    const int* lst = &g_list[z * N_NODES + t0];
    if (tid < 64) lsts[tid] = (tid < rows) ? lst[tid] : 0;
    __syncthreads();
    for (int i = tid; i < 8192; i += 256) {
        int r = i >> 7, f = i & 127;
        Xs[f * 66 + r] = (r < rows) ? X[(size_t)lsts[r] * 128 + f] : 0.0f;
    }
    __syncthreads();
    int g = tid & 127;
    int h = tid >> 7;
    const ull* Xp = (const ull*)Xs;
    ull acc[16];
    #pragma unroll
    for (int j = 0; j < 16; j++) acc[j] = 0ull;
    #pragma unroll 4
    for (int f = 0; f < 128; f++) {
        float w = Ws[f * 128 + g];
        ull wd = pack2(w, w);
        int pb = f * 33 + h * 16;
        #pragma unroll
        for (int j = 0; j < 16; j++) fma2(acc[j], Xp[pb + j], wd);
    }
    #pragma unroll
    for (int j = 0; j < 16; j++) {
        float2 v = unpack2(acc[j]);
        int m0 = h * 32 + 2 * j;
        if (m0 < rows)     Self[(size_t)lsts[m0] * 128 + g]     = v.x * INV_SQRT1280;
        if (m0 + 1 < rows) Self[(size_t)lsts[m0 + 1] * 128 + g] = v.y * INV_SQRT1280;
    }
}

// ---------------- vector-channel GEMM (SoA-transposed, f32x2) ----------------
// O[n,g,c] = sum_f X[n,f,c] W[f,g]; 16-row tile; h = tid>>7 owns 8 rows (4 pairs)
__global__ void k_gemm_v(const float* __restrict__ X, const float* __restrict__ W,
                         float* __restrict__ O, float scale) {
    extern __shared__ float sm[];
    float* Ws = sm;            // 16384
    float* Xt = sm + 16384;    // 3 planes of 128*18
    int tid = threadIdx.x;
    for (int i = tid; i < 16384; i += 256) Ws[i] = W[i];
    int base = blockIdx.x * 16;
    const float* Xrow = X + (size_t)base * 384;
    for (int i = tid; i < 2048; i += 256) {
        int n = i >> 7, f = i & 127;
        int src = n * 384 + f * 3;
        Xt[0 * 2304 + f * 18 + n] = Xrow[src + 0];
        Xt[1 * 2304 + f * 18 + n] = Xrow[src + 1];
        Xt[2 * 2304 + f * 18 + n] = Xrow[src + 2];
    }
    __syncthreads();
    int g = tid & 127;
    int h = tid >> 7;
    const ull* X0 = (const ull*)(Xt);
    const ull* X1 = (const ull*)(Xt + 2304);
    const ull* X2 = (const ull*)(Xt + 4608);
    ull acc[3][4];
    #pragma unroll
    for (int c = 0; c < 3; c++)
        #pragma unroll
        for (int j = 0; j < 4; j++) acc[c][j] = 0ull;
    #pragma unroll 4
    for (int f = 0; f < 128; f++) {
        float w = Ws[f * 128 + g];
        ull wd = pack2(w, w);
        int pb = f * 9 + h * 4;       // 18 floats = 9 ull per plane-row
        #pragma unroll
        for (int j = 0; j < 4; j++) {
            fma2(acc[0][j], X0[pb + j], wd);
            fma2(acc[1][j], X1[pb + j], wd);
            fma2(acc[2][j], X2[pb + j], wd);
        }
    }
    #pragma unroll
    for (int j = 0; j < 4; j++) {
        int n0 = base + h * 8 + 2 * j;
        #pragma unroll
        for (int c = 0; c < 3; c++) {
            float2 v = unpack2(acc[c][j]);
            O[(size_t)n0 * 384 + g * 3 + c]       = v.x * scale;
            O[(size_t)(n0 + 1) * 384 + g * 3 + c] = v.y * scale;
        }
    }
}

// ---------------- radial MLP layers 1..3 (8->64->64->64, silu, f32x2) --------
__global__ void k_mlp123(const float* __restrict__ radial,
                         const float* __restrict__ w1,
                         const float* __restrict__ w2,
                         const float* __restrict__ w3) {
    __shared__ float W1s[512];
    __shared__ float W2s[4096];
    __shared__ float W3s[4096];
    int tid = threadIdx.x;
    for (int i = tid; i < 512; i += 128) W1s[i] = w1[i];
    for (int i = tid; i < 4096; i += 128) { W2s[i] = w2[i]; W3s[i] = w3[i]; }
    int e = blockIdx.x * 128 + tid;
    float r[8];
    *(float4*)&r[0] = *(const float4*)&radial[(size_t)e * 8];
    *(float4*)&r[4] = *(const float4*)&radial[(size_t)e * 8 + 4];
    __syncthreads();
    const ull* W1u = (const ull*)W1s;
    const ull* W2u = (const ull*)W2s;
    const ull* W3u = (const ull*)W3s;

    ull acc[32];
    float l[64];
    // layer 1 (8 -> 64)
    #pragma unroll
    for (int j = 0; j < 32; j++) acc[j] = 0ull;
    #pragma unroll
    for (int k = 0; k < 8; k++) {
        ull rk = pack2(r[k], r[k]);
        #pragma unroll
        for (int j = 0; j < 32; j++) fma2(acc[j], W1u[k * 32 + j], rk);
    }
    #pragma unroll
    for (int j = 0; j < 32; j++) {
        float2 v = unpack2(acc[j]);
        l[2 * j]     = silu_f(v.x * INV_SQRT8);
        l[2 * j + 1] = silu_f(v.y * INV_SQRT8);
    }
    // layer 2 (64 -> 64)
    #pragma unroll
    for (int j = 0; j < 32; j++) acc[j] = 0ull;
    #pragma unroll 4
    for (int k = 0; k < 64; k++) {
        ull lk = pack2(l[k], l[k]);
        #pragma unroll
        for (int j = 0; j < 32; j++) fma2(acc[j], W2u[k * 32 + j], lk);
    }
    #pragma unroll
    for (int j = 0; j < 32; j++) {
        float2 v = unpack2(acc[j]);
        l[2 * j]     = silu_f(v.x * 0.125f);
        l[2 * j + 1] = silu_f(v.y * 0.125f);
    }
    // layer 3 (64 -> 64) -> transposed global
    #pragma unroll
    for (int j = 0; j < 32; j++) acc[j] = 0ull;
    #pragma unroll 4
    for (int k = 0; k < 64; k++) {
        ull lk = pack2(l[k], l[k]);
        #pragma unroll
        for (int j = 0; j < 32; j++) fma2(acc[j], W3u[k * 32 + j], lk);
    }
    #pragma unroll
    for (int j = 0; j < 32; j++) {
        float2 v = unpack2(acc[j]);
        g_h3t[(size_t)(2 * j)     * E_EDGES + e] = silu_f(v.x * 0.125f);
        g_h3t[(size_t)(2 * j + 1) * E_EDGES + e] = silu_f(v.y * 0.125f);
    }
}

// ---------------- edge kernel: MLP L4 + tensor product + scatter -------------
// 512 threads = 8 groups x 64; each group handles 4 edges; 32 edges/iteration.
// h3 staged in smem as DUPLICATED pairs (a,a) -> LDS.64 feeds fma2 directly.
__global__ void k_edge(const float* __restrict__ w4,
                       const float* __restrict__ vectors,
                       const int* __restrict__ senders,
                       const int* __restrict__ receivers) {
    extern __shared__ float sm[];
    float* W4s = sm;                              // 40960 floats
    ull*   h3d = (ull*)(sm + 40960);              // [k][e] 64*32 ull = 16KB
    float* Y1s = sm + 40960 + 4096;               // 32*4
    int*   ss  = (int*)(sm + 40960 + 4096 + 128); // 32
    int*   rr  = ss + 32;                         // 32
    const ull* W4s2 = (const ull*)W4s;

    int t  = threadIdx.x;
    int gr = t >> 6;        // 0..7
    int c2 = t & 63;        // channel pair index

    for (int i = t; i < 40960; i += 512) W4s[i] = w4[i];
    __syncthreads();

    int ngroups = E_EDGES / 32;
    for (int gi = blockIdx.x; gi < ngroups; gi += gridDim.x) {
        int eb = gi * 32;
        __syncthreads();
        for (int i = t; i < 2048; i += 512) {
            int k = i >> 5, e = i & 31;
            float v = g_h3t[(size_t)k * E_EDGES + eb + e];
            h3d[k * 32 + e] = pack2(v, v);
        }
        if (t < 32) {
            int e = eb + t;
            ss[t] = senders[e];
            rr[t] = receivers[e];
            float vx = vectors[e * 3], vy = vectors[e * 3 + 1], vz = vectors[e * 3 + 2];
            float inv = 1.0f / (sqrtf(vx * vx + vy * vy + vz * vz) + 1e-9f);
            Y1s[t * 4 + 0] = vx * inv; Y1s[t * 4 + 1] = vy * inv; Y1s[t * 4 + 2] = vz * inv;
        }
        __syncthreads();

        ull acc[5][4];
        #pragma unroll
        for (int p = 0; p < 5; p++)
            #pragma unroll
            for (int ee = 0; ee < 4; ee++) acc[p][ee] = 0ull;

        #pragma unroll 2
        for (int k = 0; k < 64; k++) {
            ull av[4];
            #pragma unroll
            for (int ee = 0; ee < 4; ee++) av[ee] = h3d[k * 32 + gr * 4 + ee];
            #pragma unroll
            for (int p = 0; p < 5; p++) {
                ull w = W4s2[k * 320 + p * 64 + c2];
                #pragma unroll
                for (int ee = 0; ee < 4; ee++) fma2(acc[p][ee], w, av[ee]);
            }
        }

        #pragma unroll
        for (int ee = 0; ee < 4; ee++) {
            int le = gr * 4 + ee;
            float2 m0 = unpack2(acc[0][ee]);
            float2 m1 = unpack2(acc[1][ee]);
            float2 m2 = unpack2(acc[2][ee]);
            float2 m3 = unpack2(acc[3][ee]);
            float2 m4 = unpack2(acc[4][ee]);
            m0.x *= K_MIX; m0.y *= K_MIX; m1.x *= K_MIX; m1.y *= K_MIX;
            m2.x *= K_MIX; m2.y *= K_MIX; m3.x *= K_MIX; m3.y *= K_MIX;
            m4.x *= K_MIX; m4.y *= K_MIX;
            int s   = ss[le];
            int rcv = rr[le];
            float y0 = Y1s[le * 4 + 0], y1 = Y1s[le * 4 + 1], y2 = Y1s[le * 4 + 2];

            float2 es2 = *(const float2*)&g_hs[(size_t)s * 128 + 2 * c2];
            const float* evp = &g_hv[(size_t)s * 384 + 6 * c2];
            float2 e0 = *(const float2*)(evp + 0);
            float2 e1 = *(const float2*)(evp + 2);
            float2 e2 = *(const float2*)(evp + 4);
            // channel a vector = (e0.x, e0.y, e1.x); channel b = (e1.y, e2.x, e2.y)
            float dota = e0.x * y0 + e0.y * y1 + e1.x * y2;
            float dotb = e1.y * y0 + e2.x * y1 + e2.y * y2;

            float m0a = m0.x * es2.x + m1.x * dota * INV_SQRT3F;
            float m0b = m0.y * es2.y + m1.y * dotb * INV_SQRT3F;

            // cross(ev, Y1)
            float cax = e0.y * y2 - e1.x * y1;
            float cay = e1.x * y0 - e0.x * y2;
            float caz = e0.x * y1 - e0.y * y0;
            float cbx = e2.x * y2 - e2.y * y1;
            float cby = e2.y * y0 - e1.y * y2;
            float cbz = e1.y * y1 - e2.x * y0;

            red2(&g_aggs[(size_t)rcv * 128 + 2 * c2], m0a, m0b);
            float* av_ = &g_aggv[(size_t)rcv * 384 + 6 * c2];
            red2(av_ + 0, m2.x * es2.x * y0 + m3.x * e0.x + m4.x * INV_SQRT2F * cax,
                          m2.x * es2.x * y1 + m3.x * e0.y + m4.x * INV_SQRT2F * cay);
            red2(av_ + 2, m2.x * es2.x * y2 + m3.x * e1.x + m4.x * INV_SQRT2F * caz,
                          m2.y * es2.y * y0 + m3.y * e1.y + m4.y * INV_SQRT2F * cbx);
            red2(av_ + 4, m2.y * es2.y * y1 + m3.y * e2.x + m4.y * INV_SQRT2F * cby,
                          m2.y * es2.y * y2 + m3.y * e2.y + m4.y * INV_SQRT2F * cbz);
        }
    }
}

// ---------------- symmetric contraction features -----------------------------
__global__ void k_feats(const float* __restrict__ w_sc, const int* __restrict__ species) {
    int t = threadIdx.x;
    int n = blockIdx.x * 2 + (t >> 7);
    int f = t & 127;
    int z = species[n];
    float w0 = w_sc[z * 384 + f]        * INV_SQRT10F;
    float w1 = w_sc[z * 384 + 128 + f]  * INV_SQRT10F;
    float w2 = w_sc[z * 384 + 256 + f]  * INV_SQRT10F;
    float xs = g_xs[(size_t)n * 128 + f];
    const float* xv = &g_xv[(size_t)n * 384 + f * 3];
    float vv = xv[0] * xv[0] + xv[1] * xv[1] + xv[2] * xv[2];
    g_tmp[(size_t)n * 128 + f] = w0 * xs + w1 * xs * xs + w2 * vv;
}

// ---------------- readout ----------------------------------------------------
__global__ void k_read(const float* __restrict__ feats,
                       const float* __restrict__ w_read1,
                       const float* __restrict__ w_read2,
                       float* __restrict__ out) {
    __shared__ float w1s[2048];
    __shared__ float fs[16 * 132];
    int t = threadIdx.x;
    int nb = blockIdx.x * 16;
    for (int i = t; i < 2048; i += 256) w1s[i] = w_read1[i];
    for (int i = t; i < 2048; i += 256) {
        int node = i >> 7, c = i & 127;
        fs[node * 132 + c] = feats[(size_t)(nb + node) * 128 + c];
    }
    __syncthreads();
    int r = t >> 4, j = t & 15;
    float acc = 0.f;
    #pragma unroll 4
    for (int f = 0; f < 128; f++) acc += fs[r * 132 + f] * w1s[f * 16 + j];
    float a = silu_f(acc * INV_SQRT128) * w_read2[j] * 0.25f;
    #pragma unroll
    for (int m = 8; m; m >>= 1) a += __shfl_xor_sync(0xffffffffu, a, m);
    if (j == 0) out[nb + r] = a;
}

// ---------------- launch -----------------------------------------------------
extern "C" void kernel_launch(void* const* d_in, const int* in_sizes, int n_in,
                              void* d_out, int out_size) {
    const float* vectors      = (const float*)d_in[0];
    const float* node_scalars = (const float*)d_in[1];
    const float* node_vectors = (const float*)d_in[2];
    const float* radial       = (const float*)d_in[3];
    const float* w_skip       = (const float*)d_in[4];
    const float* w_up0        = (const float*)d_in[5];
    const float* w_up1        = (const float*)d_in[6];
    const float* mlp_w1       = (const float*)d_in[7];
    const float* mlp_w2       = (const float*)d_in[8];
    const float* mlp_w3       = (const float*)d_in[9];
    const float* mlp_w4       = (const float*)d_in[10];
    const float* w_down0      = (const float*)d_in[11];
    const float* w_down1      = (const float*)d_in[12];
    const float* w_sc         = (const float*)d_in[13];
    const float* w_post       = (const float*)d_in[14];
    const float* w_read1      = (const float*)d_in[15];
    const float* w_read2      = (const float*)d_in[16];
    const int*   senders      = (const int*)d_in[17];
    const int*   receivers    = (const int*)d_in[18];
    const int*   species      = (const int*)d_in[19];

    float* out   = (float*)d_out;            // [N] energies
    float* feats = (float*)d_out + N_NODES;  // [N,128] feats

    float *hs, *hv, *selfc, *aggs, *aggv, *xs, *xv, *tmp;
    int   *cnt;
    cudaGetSymbolAddress((void**)&hs,    g_hs);
    cudaGetSymbolAddress((void**)&hv,    g_hv);
    cudaGetSymbolAddress((void**)&selfc, g_self);
    cudaGetSymbolAddress((void**)&aggs,  g_aggs);
    cudaGetSymbolAddress((void**)&aggv,  g_aggv);
    cudaGetSymbolAddress((void**)&xs,    g_xs);
    cudaGetSymbolAddress((void**)&xv,    g_xv);
    cudaGetSymbolAddress((void**)&tmp,   g_tmp);
    cudaGetSymbolAddress((void**)&cnt,   g_cnt);

    const int SM_GEMM_S = (16384 + 128 * 66) * 4;        // ~99KB
    const int SM_GEMM_V = (16384 + 3 * 2304) * 4;        // ~93KB
    const int SM_EDGE   = (40960 + 4096 + 128 + 64) * 4; // ~181KB

    cudaFuncSetAttribute(k_gemm_s,  cudaFuncAttributeMaxDynamicSharedMemorySize, SM_GEMM_S);
    cudaFuncSetAttribute(k_gemm_sc, cudaFuncAttributeMaxDynamicSharedMemorySize, SM_GEMM_S);
    cudaFuncSetAttribute(k_gemm_v,  cudaFuncAttributeMaxDynamicSharedMemorySize, SM_GEMM_V);
    cudaFuncSetAttribute(k_edge,    cudaFuncAttributeMaxDynamicSharedMemorySize, SM_EDGE);

    cudaMemsetAsync(aggs, 0, (size_t)N_NODES * F_CH * 4);
    cudaMemsetAsync(aggv, 0, (size_t)N_NODES * F_CH * 12);
    cudaMemsetAsync(cnt,  0, Z_SP * 4);

    k_species_list<<<N_NODES / 256, 256>>>(species);
    k_gemm_sc<<<dim3(512, Z_SP), 256, SM_GEMM_S>>>(node_scalars, w_skip, selfc);
    k_gemm_s<<<512, 256, SM_GEMM_S>>>(node_scalars, w_up0, hs, (const float*)0, INV_SQRT128);
    k_gemm_v<<<N_NODES / 16, 256, SM_GEMM_V>>>(node_vectors, w_up1, hv, INV_SQRT128);
    k_mlp123<<<E_EDGES / 128, 128>>>(radial, mlp_w1, mlp_w2, mlp_w3);
    k_edge<<<148, 512, SM_EDGE>>>(mlp_w4, vectors, senders, receivers);
    k_gemm_s<<<512, 256, SM_GEMM_S>>>(aggs, w_down0, xs, (const float*)0, INV_SQRT128);
    k_gemm_v<<<N_NODES / 16, 256, SM_GEMM_V>>>(aggv, w_down1, xv, INV_SQRT128);
    k_feats<<<N_NODES / 2, 256>>>(w_sc, species);
    k_gemm_s<<<512, 256, SM_GEMM_S>>>(tmp, w_post, feats, selfc, INV_SQRT128);
    k_read<<<N_NODES / 16, 256>>>(feats, w_read1, w_read2, out);
}

// round 14
// speedup vs baseline: 1.3310x; 1.3310x over previous
#include <cuda_runtime.h>
#include <math.h>

#define N_NODES 32768
#define E_EDGES 524288
#define F_CH    128
#define Z_SP    10

typedef unsigned long long ull;

// ---------------- scratch (static device globals; no allocation) -------------
__device__ float g_hs  [N_NODES * F_CH];
__device__ float g_hv  [N_NODES * F_CH * 3];
__device__ float g_self[N_NODES * F_CH];
__device__ float g_h3t [64 * E_EDGES];        // transposed [k][e]
__device__ float g_aggs[N_NODES * F_CH];
__device__ float g_aggv[N_NODES * F_CH * 3];
__device__ float g_xs  [N_NODES * F_CH];
__device__ float g_xv  [N_NODES * F_CH * 3];
__device__ float g_tmp [N_NODES * F_CH];
__device__ int   g_cnt [Z_SP];
__device__ int   g_list[Z_SP * N_NODES];

#define INV_SQRT128  0.08838834764831845f
#define INV_SQRT1280 0.027950849718747372f
#define INV_SQRT8    0.35355339059327373f
#define INV_SQRT3F   0.5773502691896258f
#define INV_SQRT2F   0.7071067811865476f
#define INV_SQRT10F  0.31622776601683794f
#define K_MIX        0.015625f   /* inv(w4)=1/8 times EPS=1/8 */

__device__ __forceinline__ float silu_f(float x) {
    return x * (1.0f / (1.0f + __expf(-x)));
}
__device__ __forceinline__ ull pack2(float x, float y) {
    ull r; asm("mov.b64 %0, {%1, %2};" : "=l"(r) : "f"(x), "f"(y)); return r;
}
__device__ __forceinline__ float2 unpack2(ull v) {
    float2 r; asm("mov.b64 {%0, %1}, %2;" : "=f"(r.x), "=f"(r.y) : "l"(v)); return r;
}
__device__ __forceinline__ void fma2(ull &d, ull a, ull b) {
    asm("fma.rn.f32x2 %0, %1, %2, %0;" : "+l"(d) : "l"(a), "l"(b));
}

// ---------------- species bucketing ------------------------------------------
__global__ void k_species_list(const int* __restrict__ species) {
    int n = blockIdx.x * 256 + threadIdx.x;
    if (n < N_NODES) {
        int z = species[n];
        int pos = atomicAdd(&g_cnt[z], 1);
        g_list[z * N_NODES + pos] = n;
    }
}

// ---------------- scalar-channel GEMM [rows,128]@[128,128], 256 thr ----------
// (R9 version — measured good)
__global__ void k_gemm_s(const float* __restrict__ X, const float* __restrict__ W,
                         float* __restrict__ O, const float* __restrict__ Add,
                         float scale) {
    extern __shared__ float sm[];
    float* Ws = sm;           // 128*128
    float* Xs = sm + 16384;   // 64 rows * 130 stride
    int tid = threadIdx.x;
    for (int i = tid; i < 16384; i += 256) Ws[i] = W[i];
    int base = blockIdx.x * 64;
    const float* Xrow = X + (size_t)base * 128;
    for (int i = tid; i < 8192; i += 256) Xs[(i >> 7) * 130 + (i & 127)] = Xrow[i];
    __syncthreads();
    int g = tid & 127;
    int h = tid >> 7;
    for (int m0 = h * 32; m0 < h * 32 + 32; m0 += 8) {
        float acc[8] = {0,0,0,0,0,0,0,0};
        #pragma unroll 4
        for (int f = 0; f < 128; f++) {
            float w = Ws[f * 128 + g];
            #pragma unroll
            for (int r = 0; r < 8; r++) acc[r] += Xs[(m0 + r) * 130 + f] * w;
        }
        #pragma unroll
        for (int r = 0; r < 8; r++) {
            int n = base + m0 + r;
            float v = acc[r] * scale;
            if (Add) v += Add[(size_t)n * 128 + g];
            O[(size_t)n * 128 + g] = v;
        }
    }
}

// ---------------- species-indexed skip GEMM (256 thr, R9 version) ------------
__global__ void k_gemm_sc(const float* __restrict__ X, const float* __restrict__ w_skip,
                          float* __restrict__ Self) {
    extern __shared__ float sm[];
    float* Ws = sm;
    float* Xs = sm + 16384;
    int z = blockIdx.y;
    int cnt = g_cnt[z];
    int t0 = blockIdx.x * 64;
    if (t0 >= cnt) return;
    int tid = threadIdx.x;
    const float* W = w_skip + z * 16384;
    for (int i = tid; i < 16384; i += 256) Ws[i] = W[i];
    int rows = cnt - t0; if (rows > 64) rows = 64;
    const int* lst = &g_list[z * N_NODES + t0];
    for (int i = tid; i < rows * 128; i += 256) {
        int rr = i >> 7;
        Xs[rr * 130 + (i & 127)] = X[(size_t)lst[rr] * 128 + (i & 127)];
    }
    __syncthreads();
    int g = tid & 127;
    int h = tid >> 7;
    for (int m0 = h * 32; m0 < h * 32 + 32; m0 += 8) {
        if (m0 >= rows) break;
        float acc[8] = {0,0,0,0,0,0,0,0};
        #pragma unroll 4
        for (int f = 0; f < 128; f++) {
            float w = Ws[f * 128 + g];
            #pragma unroll
            for (int r = 0; r < 8; r++) acc[r] += Xs[(m0 + r) * 130 + f] * w;
        }
        #pragma unroll
        for (int r = 0; r < 8; r++) {
            int m = m0 + r;
            if (m < rows) Self[(size_t)lst[m] * 128 + g] = acc[r] * INV_SQRT1280;
        }
    }
}

// ---------------- vector-channel GEMM (256 thr, 16-row tile, R9 version) -----
__global__ void k_gemm_v(const float* __restrict__ X, const float* __restrict__ W,
                         float* __restrict__ O, float scale) {
    extern __shared__ float sm[];
    float* Ws = sm;           // 16384
    float* Xv = sm + 16384;   // 16*384
    int tid = threadIdx.x;
    for (int i = tid; i < 16384; i += 256) Ws[i] = W[i];
    int base = blockIdx.x * 16;
    const float* Xrow = X + (size_t)base * 384;
    for (int i = tid; i < 6144; i += 256) Xv[i] = Xrow[i];
    __syncthreads();
    int g = tid & 127;
    int h = tid >> 7;
    for (int m0 = h * 8; m0 < h * 8 + 8; m0 += 4) {
        float acc[4][3] = {};
        #pragma unroll 2
        for (int f = 0; f < 128; f++) {
            float w = Ws[f * 128 + g];
            #pragma unroll
            for (int r = 0; r < 4; r++) {
                int bo = (m0 + r) * 384 + f * 3;
                acc[r][0] += Xv[bo + 0] * w;
                acc[r][1] += Xv[bo + 1] * w;
                acc[r][2] += Xv[bo + 2] * w;
            }
        }
        #pragma unroll
        for (int r = 0; r < 4; r++) {
            size_t ob = (size_t)(base + m0 + r) * 384 + g * 3;
            O[ob + 0] = acc[r][0] * scale;
            O[ob + 1] = acc[r][1] * scale;
            O[ob + 2] = acc[r][2] * scale;
        }
    }
}

// ---------------- radial MLP layers 1..3 (8->64->64->64, silu, f32x2) --------
__global__ void k_mlp123(const float* __restrict__ radial,
                         const float* __restrict__ w1,
                         const float* __restrict__ w2,
                         const float* __restrict__ w3) {
    __shared__ float W1s[512];
    __shared__ float W2s[4096];
    __shared__ float W3s[4096];
    int tid = threadIdx.x;
    for (int i = tid; i < 512; i += 128) W1s[i] = w1[i];
    for (int i = tid; i < 4096; i += 128) { W2s[i] = w2[i]; W3s[i] = w3[i]; }
    int e = blockIdx.x * 128 + tid;
    float r[8];
    *(float4*)&r[0] = *(const float4*)&radial[(size_t)e * 8];
    *(float4*)&r[4] = *(const float4*)&radial[(size_t)e * 8 + 4];
    __syncthreads();
    const ull* W1u = (const ull*)W1s;
    const ull* W2u = (const ull*)W2s;
    const ull* W3u = (const ull*)W3s;

    ull acc[32];
    float l[64];
    // layer 1 (8 -> 64)
    #pragma unroll
    for (int j = 0; j < 32; j++) acc[j] = 0ull;
    #pragma unroll
    for (int k = 0; k < 8; k++) {
        ull rk = pack2(r[k], r[k]);
        #pragma unroll
        for (int j = 0; j < 32; j++) fma2(acc[j], W1u[k * 32 + j], rk);
    }
    #pragma unroll
    for (int j = 0; j < 32; j++) {
        float2 v = unpack2(acc[j]);
        l[2 * j]     = silu_f(v.x * INV_SQRT8);
        l[2 * j + 1] = silu_f(v.y * INV_SQRT8);
    }
    // layer 2 (64 -> 64)
    #pragma unroll
    for (int j = 0; j < 32; j++) acc[j] = 0ull;
    #pragma unroll 4
    for (int k = 0; k < 64; k++) {
        ull lk = pack2(l[k], l[k]);
        #pragma unroll
        for (int j = 0; j < 32; j++) fma2(acc[j], W2u[k * 32 + j], lk);
    }
    #pragma unroll
    for (int j = 0; j < 32; j++) {
        float2 v = unpack2(acc[j]);
        l[2 * j]     = silu_f(v.x * 0.125f);
        l[2 * j + 1] = silu_f(v.y * 0.125f);
    }
    // layer 3 (64 -> 64) -> transposed global
    #pragma unroll
    for (int j = 0; j < 32; j++) acc[j] = 0ull;
    #pragma unroll 4
    for (int k = 0; k < 64; k++) {
        ull lk = pack2(l[k], l[k]);
        #pragma unroll
        for (int j = 0; j < 32; j++) fma2(acc[j], W3u[k * 32 + j], lk);
    }
    #pragma unroll
    for (int j = 0; j < 32; j++) {
        float2 v = unpack2(acc[j]);
        g_h3t[(size_t)(2 * j)     * E_EDGES + e] = silu_f(v.x * 0.125f);
        g_h3t[(size_t)(2 * j + 1) * E_EDGES + e] = silu_f(v.y * 0.125f);
    }
}

// ---------------- edge kernel: MLP L4 + tensor product + scatter -------------
// CHANNEL-SPLIT: grid (148, 2). blockIdx.y selects channel half (64 of 128).
// W4 stage is halved (80KB) -> ~91KB smem -> 2 blocks/SM -> 32 warps/SM.
// 512 threads = 16 groups x 32; each group handles 2 edges; 32 edges/iter.
__global__ void __launch_bounds__(512, 2)
k_edge(const float* __restrict__ w4,
       const float* __restrict__ vectors,
       const int* __restrict__ senders,
       const int* __restrict__ receivers) {
    extern __shared__ float sm[];
    float* W4s = sm;                               // 20480 floats (half)
    float* h3s = sm + 20480;                       // 32 * 66
    float* Y1s = sm + 20480 + 2112;                // 32 * 4
    int*   ss  = (int*)(sm + 20480 + 2112 + 128);  // 32
    int*   rr  = ss + 32;                          // 32
    const ull* W4s2 = (const ull*)W4s;

    int t    = threadIdx.x;
    int half = blockIdx.y;
    int gr   = t >> 5;          // 0..15
    int c2l  = t & 31;          // local channel pair
    int c2   = half * 32 + c2l; // global channel pair (0..63)

    // stage this block's half of w4: W4s[(k*5+p)*64 + jj] = w4[k*640 + p*128 + 64*half + jj]
    for (int i = t; i < 20480; i += 512) {
        int k  = i / 320;
        int j  = i - k * 320;
        int p  = j >> 6;
        int jj = j & 63;
        W4s[i] = w4[k * 640 + p * 128 + half * 64 + jj];
    }
    __syncthreads();

    int ngroups = E_EDGES / 32;
    for (int gi = blockIdx.x; gi < ngroups; gi += gridDim.x) {
        int eb = gi * 32;
        __syncthreads();
        for (int i = t; i < 2048; i += 512) {
            int k = i >> 5, e = i & 31;
            h3s[e * 66 + k] = g_h3t[(size_t)k * E_EDGES + eb + e];
        }
        if (t < 32) {
            int e = eb + t;
            ss[t] = senders[e];
            rr[t] = receivers[e];
            float vx = vectors[e * 3], vy = vectors[e * 3 + 1], vz = vectors[e * 3 + 2];
            float inv = 1.0f / (sqrtf(vx * vx + vy * vy + vz * vz) + 1e-9f);
            Y1s[t * 4 + 0] = vx * inv; Y1s[t * 4 + 1] = vy * inv; Y1s[t * 4 + 2] = vz * inv;
        }
        __syncthreads();

        ull acc[5][2];
        #pragma unroll
        for (int p = 0; p < 5; p++)
            #pragma unroll
            for (int ee = 0; ee < 2; ee++) acc[p][ee] = 0ull;

        #pragma unroll 2
        for (int k = 0; k < 64; k++) {
            ull av[2];
            #pragma unroll
            for (int ee = 0; ee < 2; ee++) {
                float a = h3s[(gr * 2 + ee) * 66 + k];
                av[ee] = pack2(a, a);
            }
            #pragma unroll
            for (int p = 0; p < 5; p++) {
                ull w = W4s2[k * 160 + p * 32 + c2l];
                #pragma unroll
                for (int ee = 0; ee < 2; ee++) fma2(acc[p][ee], w, av[ee]);
            }
        }

        #pragma unroll
        for (int ee = 0; ee < 2; ee++) {
            int le = gr * 2 + ee;
            float2 m0 = unpack2(acc[0][ee]);
            float2 m1 = unpack2(acc[1][ee]);
            float2 m2 = unpack2(acc[2][ee]);
            float2 m3 = unpack2(acc[3][ee]);
            float2 m4 = unpack2(acc[4][ee]);
            m0.x *= K_MIX; m0.y *= K_MIX; m1.x *= K_MIX; m1.y *= K_MIX;
            m2.x *= K_MIX; m2.y *= K_MIX; m3.x *= K_MIX; m3.y *= K_MIX;
            m4.x *= K_MIX; m4.y *= K_MIX;
            int s   = ss[le];
            int rcv = rr[le];
            float y0 = Y1s[le * 4 + 0], y1 = Y1s[le * 4 + 1], y2 = Y1s[le * 4 + 2];

            float2 es2 = *(const float2*)&g_hs[(size_t)s * 128 + 2 * c2];
            const float* evp = &g_hv[(size_t)s * 384 + 6 * c2];
            float2 e0 = *(const float2*)(evp + 0);
            float2 e1 = *(const float2*)(evp + 2);
            float2 e2 = *(const float2*)(evp + 4);
            // channel a vector = (e0.x, e0.y, e1.x); channel b = (e1.y, e2.x, e2.y)
            float dota = e0.x * y0 + e0.y * y1 + e1.x * y2;
            float dotb = e1.y * y0 + e2.x * y1 + e2.y * y2;

            float m0a = m0.x * es2.x + m1.x * dota * INV_SQRT3F;
            float m0b = m0.y * es2.y + m1.y * dotb * INV_SQRT3F;

            // cross(ev, Y1)
            float cax = e0.y * y2 - e1.x * y1;
            float cay = e1.x * y0 - e0.x * y2;
            float caz = e0.x * y1 - e0.y * y0;
            float cbx = e2.x * y2 - e2.y * y1;
            float cby = e2.y * y0 - e1.y * y2;
            float cbz = e1.y * y1 - e2.x * y0;

            float* as = &g_aggs[(size_t)rcv * 128 + 2 * c2];
            atomicAdd(as + 0, m0a);
            atomicAdd(as + 1, m0b);
            float* av_ = &g_aggv[(size_t)rcv * 384 + 6 * c2];
            atomicAdd(av_ + 0, m2.x * es2.x * y0 + m3.x * e0.x + m4.x * INV_SQRT2F * cax);
            atomicAdd(av_ + 1, m2.x * es2.x * y1 + m3.x * e0.y + m4.x * INV_SQRT2F * cay);
            atomicAdd(av_ + 2, m2.x * es2.x * y2 + m3.x * e1.x + m4.x * INV_SQRT2F * caz);
            atomicAdd(av_ + 3, m2.y * es2.y * y0 + m3.y * e1.y + m4.y * INV_SQRT2F * cbx);
            atomicAdd(av_ + 4, m2.y * es2.y * y1 + m3.y * e2.x + m4.y * INV_SQRT2F * cby);
            atomicAdd(av_ + 5, m2.y * es2.y * y2 + m3.y * e2.y + m4.y * INV_SQRT2F * cbz);
        }
    }
}

// ---------------- symmetric contraction features -----------------------------
__global__ void k_feats(const float* __restrict__ w_sc, const int* __restrict__ species) {
    int t = threadIdx.x;
    int n = blockIdx.x * 2 + (t >> 7);
    int f = t & 127;
    int z = species[n];
    float w0 = w_sc[z * 384 + f]        * INV_SQRT10F;
    float w1 = w_sc[z * 384 + 128 + f]  * INV_SQRT10F;
    float w2 = w_sc[z * 384 + 256 + f]  * INV_SQRT10F;
    float xs = g_xs[(size_t)n * 128 + f];
    const float* xv = &g_xv[(size_t)n * 384 + f * 3];
    float vv = xv[0] * xv[0] + xv[1] * xv[1] + xv[2] * xv[2];
    g_tmp[(size_t)n * 128 + f] = w0 * xs + w1 * xs * xs + w2 * vv;
}

// ---------------- readout ----------------------------------------------------
__global__ void k_read(const float* __restrict__ feats,
                       const float* __restrict__ w_read1,
                       const float* __restrict__ w_read2,
                       float* __restrict__ out) {
    __shared__ float w1s[2048];
    __shared__ float fs[16 * 132];
    int t = threadIdx.x;
    int nb = blockIdx.x * 16;
    for (int i = t; i < 2048; i += 256) w1s[i] = w_read1[i];
    for (int i = t; i < 2048; i += 256) {
        int node = i >> 7, c = i & 127;
        fs[node * 132 + c] = feats[(size_t)(nb + node) * 128 + c];
    }
    __syncthreads();
    int r = t >> 4, j = t & 15;
    float acc = 0.f;
    #pragma unroll 4
    for (int f = 0; f < 128; f++) acc += fs[r * 132 + f] * w1s[f * 16 + j];
    float a = silu_f(acc * INV_SQRT128) * w_read2[j] * 0.25f;
    #pragma unroll
    for (int m = 8; m; m >>= 1) a += __shfl_xor_sync(0xffffffffu, a, m);
    if (j == 0) out[nb + r] = a;
}

// ---------------- launch -----------------------------------------------------
extern "C" void kernel_launch(void* const* d_in, const int* in_sizes, int n_in,
                              void* d_out, int out_size) {
    const float* vectors      = (const float*)d_in[0];
    const float* node_scalars = (const float*)d_in[1];
    const float* node_vectors = (const float*)d_in[2];
    const float* radial       = (const float*)d_in[3];
    const float* w_skip       = (const float*)d_in[4];
    const float* w_up0        = (const float*)d_in[5];
    const float* w_up1        = (const float*)d_in[6];
    const float* mlp_w1       = (const float*)d_in[7];
    const float* mlp_w2       = (const float*)d_in[8];
    const float* mlp_w3       = (const float*)d_in[9];
    const float* mlp_w4       = (const float*)d_in[10];
    const float* w_down0      = (const float*)d_in[11];
    const float* w_down1      = (const float*)d_in[12];
    const float* w_sc         = (const float*)d_in[13];
    const float* w_post       = (const float*)d_in[14];
    const float* w_read1      = (const float*)d_in[15];
    const float* w_read2      = (const float*)d_in[16];
    const int*   senders      = (const int*)d_in[17];
    const int*   receivers    = (const int*)d_in[18];
    const int*   species      = (const int*)d_in[19];

    float* out   = (float*)d_out;            // [N] energies
    float* feats = (float*)d_out + N_NODES;  // [N,128] feats

    float *hs, *hv, *selfc, *aggs, *aggv, *xs, *xv, *tmp;
    int   *cnt;
    cudaGetSymbolAddress((void**)&hs,    g_hs);
    cudaGetSymbolAddress((void**)&hv,    g_hv);
    cudaGetSymbolAddress((void**)&selfc, g_self);
    cudaGetSymbolAddress((void**)&aggs,  g_aggs);
    cudaGetSymbolAddress((void**)&aggv,  g_aggv);
    cudaGetSymbolAddress((void**)&xs,    g_xs);
    cudaGetSymbolAddress((void**)&xv,    g_xv);
    cudaGetSymbolAddress((void**)&tmp,   g_tmp);
    cudaGetSymbolAddress((void**)&cnt,   g_cnt);

    const int SM_GEMM_S = (16384 + 64 * 130) * 4;
    const int SM_GEMM_V = (16384 + 6144) * 4;
    const int SM_EDGE   = (20480 + 2112 + 128 + 64) * 4;   // ~91KB

    cudaFuncSetAttribute(k_gemm_s,  cudaFuncAttributeMaxDynamicSharedMemorySize, SM_GEMM_S);
    cudaFuncSetAttribute(k_gemm_sc, cudaFuncAttributeMaxDynamicSharedMemorySize, SM_GEMM_S);
    cudaFuncSetAttribute(k_gemm_v,  cudaFuncAttributeMaxDynamicSharedMemorySize, SM_GEMM_V);
    cudaFuncSetAttribute(k_edge,    cudaFuncAttributeMaxDynamicSharedMemorySize, SM_EDGE);

    cudaMemsetAsync(aggs, 0, (size_t)N_NODES * F_CH * 4);
    cudaMemsetAsync(aggv, 0, (size_t)N_NODES * F_CH * 12);
    cudaMemsetAsync(cnt,  0, Z_SP * 4);

    k_species_list<<<N_NODES / 256, 256>>>(species);
    k_gemm_sc<<<dim3(512, Z_SP), 256, SM_GEMM_S>>>(node_scalars, w_skip, selfc);
    k_gemm_s<<<512, 256, SM_GEMM_S>>>(node_scalars, w_up0, hs, (const float*)0, INV_SQRT128);
    k_gemm_v<<<N_NODES / 16, 256, SM_GEMM_V>>>(node_vectors, w_up1, hv, INV_SQRT128);
    k_mlp123<<<E_EDGES / 128, 128>>>(radial, mlp_w1, mlp_w2, mlp_w3);
    k_edge<<<dim3(148, 2), 512, SM_EDGE>>>(mlp_w4, vectors, senders, receivers);
    k_gemm_s<<<512, 256, SM_GEMM_S>>>(aggs, w_down0, xs, (const float*)0, INV_SQRT128);
    k_gemm_v<<<N_NODES / 16, 256, SM_GEMM_V>>>(aggv, w_down1, xv, INV_SQRT128);
    k_feats<<<N_NODES / 2, 256>>>(w_sc, species);
    k_gemm_s<<<512, 256, SM_GEMM_S>>>(tmp, w_post, feats, selfc, INV_SQRT128);
    k_read<<<N_NODES / 16, 256>>>(feats, w_read1, w_read2, out);
}

// round 15
// speedup vs baseline: 1.5385x; 1.1559x over previous
#include <cuda_runtime.h>
#include <math.h>

#define N_NODES 32768
#define E_EDGES 524288
#define F_CH    128
#define Z_SP    10

typedef unsigned long long ull;

// ---------------- scratch (static device globals; no allocation) -------------
__device__ float g_hs  [N_NODES * F_CH];
__device__ float g_hv  [N_NODES * F_CH * 3];
__device__ float g_self[N_NODES * F_CH];
__device__ float g_h3t [64 * E_EDGES];        // transposed [k][e]
__device__ float g_aggs[N_NODES * F_CH];
__device__ float g_aggv[N_NODES * F_CH * 3];
__device__ float g_xs  [N_NODES * F_CH];
__device__ float g_xv  [N_NODES * F_CH * 3];
__device__ float g_tmp [N_NODES * F_CH];
__device__ int   g_cnt [Z_SP];
__device__ int   g_list[Z_SP * N_NODES];

#define INV_SQRT128  0.08838834764831845f
#define INV_SQRT1280 0.027950849718747372f
#define INV_SQRT8    0.35355339059327373f
#define INV_SQRT3F   0.5773502691896258f
#define INV_SQRT2F   0.7071067811865476f
#define INV_SQRT10F  0.31622776601683794f
#define K_MIX        0.015625f   /* inv(w4)=1/8 times EPS=1/8 */

__device__ __forceinline__ float silu_f(float x) {
    return x * (1.0f / (1.0f + __expf(-x)));
}
__device__ __forceinline__ ull pack2(float x, float y) {
    ull r; asm("mov.b64 %0, {%1, %2};" : "=l"(r) : "f"(x), "f"(y)); return r;
}
__device__ __forceinline__ float2 unpack2(ull v) {
    float2 r; asm("mov.b64 {%0, %1}, %2;" : "=f"(r.x), "=f"(r.y) : "l"(v)); return r;
}
__device__ __forceinline__ void fma2(ull &d, ull a, ull b) {
    asm("fma.rn.f32x2 %0, %1, %2, %0;" : "+l"(d) : "l"(a), "l"(b));
}

// ---------------- species bucketing ------------------------------------------
__global__ void k_species_list(const int* __restrict__ species) {
    int n = blockIdx.x * 256 + threadIdx.x;
    if (n < N_NODES) {
        int z = species[n];
        int pos = atomicAdd(&g_cnt[z], 1);
        g_list[z * N_NODES + pos] = n;
    }
}

// ---------------- scalar-channel GEMM [rows,128]@[128,128], 256 thr ----------
__global__ void k_gemm_s(const float* __restrict__ X, const float* __restrict__ W,
                         float* __restrict__ O, const float* __restrict__ Add,
                         float scale) {
    extern __shared__ float sm[];
    float* Ws = sm;           // 128*128
    float* Xs = sm + 16384;   // 64 rows * 130 stride
    int tid = threadIdx.x;
    for (int i = tid; i < 16384; i += 256) Ws[i] = W[i];
    int base = blockIdx.x * 64;
    const float* Xrow = X + (size_t)base * 128;
    for (int i = tid; i < 8192; i += 256) Xs[(i >> 7) * 130 + (i & 127)] = Xrow[i];
    __syncthreads();
    int g = tid & 127;
    int h = tid >> 7;
    for (int m0 = h * 32; m0 < h * 32 + 32; m0 += 8) {
        float acc[8] = {0,0,0,0,0,0,0,0};
        #pragma unroll 4
        for (int f = 0; f < 128; f++) {
            float w = Ws[f * 128 + g];
            #pragma unroll
            for (int r = 0; r < 8; r++) acc[r] += Xs[(m0 + r) * 130 + f] * w;
        }
        #pragma unroll
        for (int r = 0; r < 8; r++) {
            int n = base + m0 + r;
            float v = acc[r] * scale;
            if (Add) v += Add[(size_t)n * 128 + g];
            O[(size_t)n * 128 + g] = v;
        }
    }
}

// ---------------- species-indexed skip GEMM (256 thr) ------------------------
__global__ void k_gemm_sc(const float* __restrict__ X, const float* __restrict__ w_skip,
                          float* __restrict__ Self) {
    extern __shared__ float sm[];
    float* Ws = sm;
    float* Xs = sm + 16384;
    int z = blockIdx.y;
    int cnt = g_cnt[z];
    int t0 = blockIdx.x * 64;
    if (t0 >= cnt) return;
    int tid = threadIdx.x;
    const float* W = w_skip + z * 16384;
    for (int i = tid; i < 16384; i += 256) Ws[i] = W[i];
    int rows = cnt - t0; if (rows > 64) rows = 64;
    const int* lst = &g_list[z * N_NODES + t0];
    for (int i = tid; i < rows * 128; i += 256) {
        int rr = i >> 7;
        Xs[rr * 130 + (i & 127)] = X[(size_t)lst[rr] * 128 + (i & 127)];
    }
    __syncthreads();
    int g = tid & 127;
    int h = tid >> 7;
    for (int m0 = h * 32; m0 < h * 32 + 32; m0 += 8) {
        if (m0 >= rows) break;
        float acc[8] = {0,0,0,0,0,0,0,0};
        #pragma unroll 4
        for (int f = 0; f < 128; f++) {
            float w = Ws[f * 128 + g];
            #pragma unroll
            for (int r = 0; r < 8; r++) acc[r] += Xs[(m0 + r) * 130 + f] * w;
        }
        #pragma unroll
        for (int r = 0; r < 8; r++) {
            int m = m0 + r;
            if (m < rows) Self[(size_t)lst[m] * 128 + g] = acc[r] * INV_SQRT1280;
        }
    }
}

// ---------------- vector-channel GEMM (256 thr, 16-row tile) -----------------
__global__ void k_gemm_v(const float* __restrict__ X, const float* __restrict__ W,
                         float* __restrict__ O, float scale) {
    extern __shared__ float sm[];
    float* Ws = sm;           // 16384
    float* Xv = sm + 16384;   // 16*384
    int tid = threadIdx.x;
    for (int i = tid; i < 16384; i += 256) Ws[i] = W[i];
    int base = blockIdx.x * 16;
    const float* Xrow = X + (size_t)base * 384;
    for (int i = tid; i < 6144; i += 256) Xv[i] = Xrow[i];
    __syncthreads();
    int g = tid & 127;
    int h = tid >> 7;
    for (int m0 = h * 8; m0 < h * 8 + 8; m0 += 4) {
        float acc[4][3] = {};
        #pragma unroll 2
        for (int f = 0; f < 128; f++) {
            float w = Ws[f * 128 + g];
            #pragma unroll
            for (int r = 0; r < 4; r++) {
                int bo = (m0 + r) * 384 + f * 3;
                acc[r][0] += Xv[bo + 0] * w;
                acc[r][1] += Xv[bo + 1] * w;
                acc[r][2] += Xv[bo + 2] * w;
            }
        }
        #pragma unroll
        for (int r = 0; r < 4; r++) {
            size_t ob = (size_t)(base + m0 + r) * 384 + g * 3;
            O[ob + 0] = acc[r][0] * scale;
            O[ob + 1] = acc[r][1] * scale;
            O[ob + 2] = acc[r][2] * scale;
        }
    }
}

// ---------------- radial MLP layers 1..3 (8->64->64->64, silu, f32x2) --------
__global__ void k_mlp123(const float* __restrict__ radial,
                         const float* __restrict__ w1,
                         const float* __restrict__ w2,
                         const float* __restrict__ w3) {
    __shared__ float W1s[512];
    __shared__ float W2s[4096];
    __shared__ float W3s[4096];
    int tid = threadIdx.x;
    for (int i = tid; i < 512; i += 128) W1s[i] = w1[i];
    for (int i = tid; i < 4096; i += 128) { W2s[i] = w2[i]; W3s[i] = w3[i]; }
    int e = blockIdx.x * 128 + tid;
    float r[8];
    *(float4*)&r[0] = *(const float4*)&radial[(size_t)e * 8];
    *(float4*)&r[4] = *(const float4*)&radial[(size_t)e * 8 + 4];
    __syncthreads();
    const ull* W1u = (const ull*)W1s;
    const ull* W2u = (const ull*)W2s;
    const ull* W3u = (const ull*)W3s;

    ull acc[32];
    float l[64];
    // layer 1 (8 -> 64)
    #pragma unroll
    for (int j = 0; j < 32; j++) acc[j] = 0ull;
    #pragma unroll
    for (int k = 0; k < 8; k++) {
        ull rk = pack2(r[k], r[k]);
        #pragma unroll
        for (int j = 0; j < 32; j++) fma2(acc[j], W1u[k * 32 + j], rk);
    }
    #pragma unroll
    for (int j = 0; j < 32; j++) {
        float2 v = unpack2(acc[j]);
        l[2 * j]     = silu_f(v.x * INV_SQRT8);
        l[2 * j + 1] = silu_f(v.y * INV_SQRT8);
    }
    // layer 2 (64 -> 64)
    #pragma unroll
    for (int j = 0; j < 32; j++) acc[j] = 0ull;
    #pragma unroll 4
    for (int k = 0; k < 64; k++) {
        ull lk = pack2(l[k], l[k]);
        #pragma unroll
        for (int j = 0; j < 32; j++) fma2(acc[j], W2u[k * 32 + j], lk);
    }
    #pragma unroll
    for (int j = 0; j < 32; j++) {
        float2 v = unpack2(acc[j]);
        l[2 * j]     = silu_f(v.x * 0.125f);
        l[2 * j + 1] = silu_f(v.y * 0.125f);
    }
    // layer 3 (64 -> 64) -> transposed global
    #pragma unroll
    for (int j = 0; j < 32; j++) acc[j] = 0ull;
    #pragma unroll 4
    for (int k = 0; k < 64; k++) {
        ull lk = pack2(l[k], l[k]);
        #pragma unroll
        for (int j = 0; j < 32; j++) fma2(acc[j], W3u[k * 32 + j], lk);
    }
    #pragma unroll
    for (int j = 0; j < 32; j++) {
        float2 v = unpack2(acc[j]);
        g_h3t[(size_t)(2 * j)     * E_EDGES + e] = silu_f(v.x * 0.125f);
        g_h3t[(size_t)(2 * j + 1) * E_EDGES + e] = silu_f(v.y * 0.125f);
    }
}

// ---------------- edge kernel: MLP L4 + tensor product + scatter -------------
// 512 threads = 8 groups x 64; each group handles 8 edges; 64 edges/iteration.
// Amortizes the 5 W4 LDS.64 over 8 edges -> fma2 pipe (not smem crossbar) binds.
__global__ void __launch_bounds__(512, 1)
k_edge(const float* __restrict__ w4,
       const float* __restrict__ vectors,
       const int* __restrict__ senders,
       const int* __restrict__ receivers) {
    extern __shared__ float sm[];
    float* W4s = sm;                               // 40960 floats
    float* h3s = sm + 40960;                       // 64 * 67 (stride 67: conflict-free)
    float* Y1s = sm + 40960 + 4288;                // 64 * 4
    int*   ss  = (int*)(sm + 40960 + 4288 + 256);  // 64
    int*   rr  = ss + 64;                          // 64
    const ull* W4s2 = (const ull*)W4s;

    int t  = threadIdx.x;
    int gr = t >> 6;        // 0..7
    int c2 = t & 63;        // channel pair index

    for (int i = t; i < 40960; i += 512) W4s[i] = w4[i];
    __syncthreads();

    int ngroups = E_EDGES / 64;
    for (int gi = blockIdx.x; gi < ngroups; gi += gridDim.x) {
        int eb = gi * 64;
        __syncthreads();
        for (int i = t; i < 4096; i += 512) {
            int k = i >> 6, e = i & 63;
            h3s[e * 67 + k] = g_h3t[(size_t)k * E_EDGES + eb + e];
        }
        if (t < 64) {
            int e = eb + t;
            ss[t] = senders[e];
            rr[t] = receivers[e];
            float vx = vectors[e * 3], vy = vectors[e * 3 + 1], vz = vectors[e * 3 + 2];
            float inv = 1.0f / (sqrtf(vx * vx + vy * vy + vz * vz) + 1e-9f);
            Y1s[t * 4 + 0] = vx * inv; Y1s[t * 4 + 1] = vy * inv; Y1s[t * 4 + 2] = vz * inv;
        }
        __syncthreads();

        ull acc[5][8];
        #pragma unroll
        for (int p = 0; p < 5; p++)
            #pragma unroll
            for (int ee = 0; ee < 8; ee++) acc[p][ee] = 0ull;

        #pragma unroll 2
        for (int k = 0; k < 64; k++) {
            ull av[8];
            #pragma unroll
            for (int ee = 0; ee < 8; ee++) {
                float a = h3s[(gr * 8 + ee) * 67 + k];
                av[ee] = pack2(a, a);
            }
            #pragma unroll
            for (int p = 0; p < 5; p++) {
                ull w = W4s2[k * 320 + p * 64 + c2];
                #pragma unroll
                for (int ee = 0; ee < 8; ee++) fma2(acc[p][ee], w, av[ee]);
            }
        }

        #pragma unroll
        for (int ee = 0; ee < 8; ee++) {
            int le = gr * 8 + ee;
            float2 m0 = unpack2(acc[0][ee]);
            float2 m1 = unpack2(acc[1][ee]);
            float2 m2 = unpack2(acc[2][ee]);
            float2 m3 = unpack2(acc[3][ee]);
            float2 m4 = unpack2(acc[4][ee]);
            m0.x *= K_MIX; m0.y *= K_MIX; m1.x *= K_MIX; m1.y *= K_MIX;
            m2.x *= K_MIX; m2.y *= K_MIX; m3.x *= K_MIX; m3.y *= K_MIX;
            m4.x *= K_MIX; m4.y *= K_MIX;
            int s   = ss[le];
            int rcv = rr[le];
            float y0 = Y1s[le * 4 + 0], y1 = Y1s[le * 4 + 1], y2 = Y1s[le * 4 + 2];

            float2 es2 = *(const float2*)&g_hs[(size_t)s * 128 + 2 * c2];
            const float* evp = &g_hv[(size_t)s * 384 + 6 * c2];
            float2 e0 = *(const float2*)(evp + 0);
            float2 e1 = *(const float2*)(evp + 2);
            float2 e2 = *(const float2*)(evp + 4);
            // channel a vector = (e0.x, e0.y, e1.x); channel b = (e1.y, e2.x, e2.y)
            float dota = e0.x * y0 + e0.y * y1 + e1.x * y2;
            float dotb = e1.y * y0 + e2.x * y1 + e2.y * y2;

            float m0a = m0.x * es2.x + m1.x * dota * INV_SQRT3F;
            float m0b = m0.y * es2.y + m1.y * dotb * INV_SQRT3F;

            // cross(ev, Y1)
            float cax = e0.y * y2 - e1.x * y1;
            float cay = e1.x * y0 - e0.x * y2;
            float caz = e0.x * y1 - e0.y * y0;
            float cbx = e2.x * y2 - e2.y * y1;
            float cby = e2.y * y0 - e1.y * y2;
            float cbz = e1.y * y1 - e2.x * y0;

            float* as = &g_aggs[(size_t)rcv * 128 + 2 * c2];
            atomicAdd(as + 0, m0a);
            atomicAdd(as + 1, m0b);
            float* av_ = &g_aggv[(size_t)rcv * 384 + 6 * c2];
            atomicAdd(av_ + 0, m2.x * es2.x * y0 + m3.x * e0.x + m4.x * INV_SQRT2F * cax);
            atomicAdd(av_ + 1, m2.x * es2.x * y1 + m3.x * e0.y + m4.x * INV_SQRT2F * cay);
            atomicAdd(av_ + 2, m2.x * es2.x * y2 + m3.x * e1.x + m4.x * INV_SQRT2F * caz);
            atomicAdd(av_ + 3, m2.y * es2.y * y0 + m3.y * e1.y + m4.y * INV_SQRT2F * cbx);
            atomicAdd(av_ + 4, m2.y * es2.y * y1 + m3.y * e2.x + m4.y * INV_SQRT2F * cby);
            atomicAdd(av_ + 5, m2.y * es2.y * y2 + m3.y * e2.y + m4.y * INV_SQRT2F * cbz);
        }
    }
}

// ---------------- symmetric contraction features -----------------------------
__global__ void k_feats(const float* __restrict__ w_sc, const int* __restrict__ species) {
    int t = threadIdx.x;
    int n = blockIdx.x * 2 + (t >> 7);
    int f = t & 127;
    int z = species[n];
    float w0 = w_sc[z * 384 + f]        * INV_SQRT10F;
    float w1 = w_sc[z * 384 + 128 + f]  * INV_SQRT10F;
    float w2 = w_sc[z * 384 + 256 + f]  * INV_SQRT10F;
    float xs = g_xs[(size_t)n * 128 + f];
    const float* xv = &g_xv[(size_t)n * 384 + f * 3];
    float vv = xv[0] * xv[0] + xv[1] * xv[1] + xv[2] * xv[2];
    g_tmp[(size_t)n * 128 + f] = w0 * xs + w1 * xs * xs + w2 * vv;
}

// ---------------- readout ----------------------------------------------------
__global__ void k_read(const float* __restrict__ feats,
                       const float* __restrict__ w_read1,
                       const float* __restrict__ w_read2,
                       float* __restrict__ out) {
    __shared__ float w1s[2048];
    __shared__ float fs[16 * 132];
    int t = threadIdx.x;
    int nb = blockIdx.x * 16;
    for (int i = t; i < 2048; i += 256) w1s[i] = w_read1[i];
    for (int i = t; i < 2048; i += 256) {
        int node = i >> 7, c = i & 127;
        fs[node * 132 + c] = feats[(size_t)(nb + node) * 128 + c];
    }
    __syncthreads();
    int r = t >> 4, j = t & 15;
    float acc = 0.f;
    #pragma unroll 4
    for (int f = 0; f < 128; f++) acc += fs[r * 132 + f] * w1s[f * 16 + j];
    float a = silu_f(acc * INV_SQRT128) * w_read2[j] * 0.25f;
    #pragma unroll
    for (int m = 8; m; m >>= 1) a += __shfl_xor_sync(0xffffffffu, a, m);
    if (j == 0) out[nb + r] = a;
}

// ---------------- launch -----------------------------------------------------
extern "C" void kernel_launch(void* const* d_in, const int* in_sizes, int n_in,
                              void* d_out, int out_size) {
    const float* vectors      = (const float*)d_in[0];
    const float* node_scalars = (const float*)d_in[1];
    const float* node_vectors = (const float*)d_in[2];
    const float* radial       = (const float*)d_in[3];
    const float* w_skip       = (const float*)d_in[4];
    const float* w_up0        = (const float*)d_in[5];
    const float* w_up1        = (const float*)d_in[6];
    const float* mlp_w1       = (const float*)d_in[7];
    const float* mlp_w2       = (const float*)d_in[8];
    const float* mlp_w3       = (const float*)d_in[9];
    const float* mlp_w4       = (const float*)d_in[10];
    const float* w_down0      = (const float*)d_in[11];
    const float* w_down1      = (const float*)d_in[12];
    const float* w_sc         = (const float*)d_in[13];
    const float* w_post       = (const float*)d_in[14];
    const float* w_read1      = (const float*)d_in[15];
    const float* w_read2      = (const float*)d_in[16];
    const int*   senders      = (const int*)d_in[17];
    const int*   receivers    = (const int*)d_in[18];
    const int*   species      = (const int*)d_in[19];

    float* out   = (float*)d_out;            // [N] energies
    float* feats = (float*)d_out + N_NODES;  // [N,128] feats

    float *hs, *hv, *selfc, *aggs, *aggv, *xs, *xv, *tmp;
    int   *cnt;
    cudaGetSymbolAddress((void**)&hs,    g_hs);
    cudaGetSymbolAddress((void**)&hv,    g_hv);
    cudaGetSymbolAddress((void**)&selfc, g_self);
    cudaGetSymbolAddress((void**)&aggs,  g_aggs);
    cudaGetSymbolAddress((void**)&aggv,  g_aggv);
    cudaGetSymbolAddress((void**)&xs,    g_xs);
    cudaGetSymbolAddress((void**)&xv,    g_xv);
    cudaGetSymbolAddress((void**)&tmp,   g_tmp);
    cudaGetSymbolAddress((void**)&cnt,   g_cnt);

    const int SM_GEMM_S = (16384 + 64 * 130) * 4;
    const int SM_GEMM_V = (16384 + 6144) * 4;
    const int SM_EDGE   = (40960 + 64 * 67 + 256 + 128) * 4;  // ~178KB

    cudaFuncSetAttribute(k_gemm_s,  cudaFuncAttributeMaxDynamicSharedMemorySize, SM_GEMM_S);
    cudaFuncSetAttribute(k_gemm_sc, cudaFuncAttributeMaxDynamicSharedMemorySize, SM_GEMM_S);
    cudaFuncSetAttribute(k_gemm_v,  cudaFuncAttributeMaxDynamicSharedMemorySize, SM_GEMM_V);
    cudaFuncSetAttribute(k_edge,    cudaFuncAttributeMaxDynamicSharedMemorySize, SM_EDGE);

    cudaMemsetAsync(aggs, 0, (size_t)N_NODES * F_CH * 4);
    cudaMemsetAsync(aggv, 0, (size_t)N_NODES * F_CH * 12);
    cudaMemsetAsync(cnt,  0, Z_SP * 4);

    k_species_list<<<N_NODES / 256, 256>>>(species);
    k_gemm_sc<<<dim3(512, Z_SP), 256, SM_GEMM_S>>>(node_scalars, w_skip, selfc);
    k_gemm_s<<<512, 256, SM_GEMM_S>>>(node_scalars, w_up0, hs, (const float*)0, INV_SQRT128);
    k_gemm_v<<<N_NODES / 16, 256, SM_GEMM_V>>>(node_vectors, w_up1, hv, INV_SQRT128);
    k_mlp123<<<E_EDGES / 128, 128>>>(radial, mlp_w1, mlp_w2, mlp_w3);
    k_edge<<<148, 512, SM_EDGE>>>(mlp_w4, vectors, senders, receivers);
    k_gemm_s<<<512, 256, SM_GEMM_S>>>(aggs, w_down0, xs, (const float*)0, INV_SQRT128);
    k_gemm_v<<<N_NODES / 16, 256, SM_GEMM_V>>>(aggv, w_down1, xv, INV_SQRT128);
    k_feats<<<N_NODES / 2, 256>>>(w_sc, species);
    k_gemm_s<<<512, 256, SM_GEMM_S>>>(tmp, w_post, feats, selfc, INV_SQRT128);
    k_read<<<N_NODES / 16, 256>>>(feats, w_read1, w_read2, out);
}

// round 16
// speedup vs baseline: 1.5800x; 1.0270x over previous
#include <cuda_runtime.h>
#include <math.h>

#define N_NODES 32768
#define E_EDGES 524288
#define F_CH    128
#define Z_SP    10

typedef unsigned long long ull;

// ---------------- scratch (static device globals; no allocation) -------------
__device__ float g_hs  [N_NODES * F_CH];
__device__ float g_hv  [N_NODES * F_CH * 3];
__device__ float g_self[N_NODES * F_CH];
__device__ float g_h3t [64 * E_EDGES];        // transposed [k][e]
__device__ float g_aggs[N_NODES * F_CH];
__device__ float g_aggv[N_NODES * F_CH * 3];
__device__ float g_xs  [N_NODES * F_CH];
__device__ float g_xv  [N_NODES * F_CH * 3];
__device__ float g_tmp [N_NODES * F_CH];
__device__ int   g_cnt [Z_SP];
__device__ int   g_list[Z_SP * N_NODES];

#define INV_SQRT128  0.08838834764831845f
#define INV_SQRT1280 0.027950849718747372f
#define INV_SQRT8    0.35355339059327373f
#define INV_SQRT3F   0.5773502691896258f
#define INV_SQRT2F   0.7071067811865476f
#define INV_SQRT10F  0.31622776601683794f
#define K_MIX        0.015625f   /* inv(w4)=1/8 times EPS=1/8 */

__device__ __forceinline__ float silu_f(float x) {
    return x * (1.0f / (1.0f + __expf(-x)));
}
__device__ __forceinline__ ull pack2(float x, float y) {
    ull r; asm("mov.b64 %0, {%1, %2};" : "=l"(r) : "f"(x), "f"(y)); return r;
}
__device__ __forceinline__ float2 unpack2(ull v) {
    float2 r; asm("mov.b64 {%0, %1}, %2;" : "=f"(r.x), "=f"(r.y) : "l"(v)); return r;
}
__device__ __forceinline__ void fma2(ull &d, ull a, ull b) {
    asm("fma.rn.f32x2 %0, %1, %2, %0;" : "+l"(d) : "l"(a), "l"(b));
}

// ---------------- species bucketing ------------------------------------------
__global__ void k_species_list(const int* __restrict__ species) {
    int n = blockIdx.x * 256 + threadIdx.x;
    if (n < N_NODES) {
        int z = species[n];
        int pos = atomicAdd(&g_cnt[z], 1);
        g_list[z * N_NODES + pos] = n;
    }
}

// ---------------- scalar-channel GEMM [64-row tile,128]@[128,128] ------------
// 256 thr: gq = tid&31 owns channels {gq,32+gq,64+gq,96+gq}; h = tid>>5 owns
// 8 rows. Per f: 4 w-LDS (coalesced) + 8 x-LDS (broadcast) + 32 FFMA.
__global__ void k_gemm_s(const float* __restrict__ X, const float* __restrict__ W,
                         float* __restrict__ O, const float* __restrict__ Add,
                         float scale) {
    extern __shared__ float sm[];
    float* Ws = sm;           // 128*128
    float* Xs = sm + 16384;   // 64 rows * 130 stride
    int tid = threadIdx.x;
    for (int i = tid; i < 16384; i += 256) Ws[i] = W[i];
    int base = blockIdx.x * 64;
    const float* Xrow = X + (size_t)base * 128;
    for (int i = tid; i < 8192; i += 256) Xs[(i >> 7) * 130 + (i & 127)] = Xrow[i];
    __syncthreads();
    int gq = tid & 31;
    int h  = tid >> 5;        // 0..7, rows [8h, 8h+8)
    int m0 = h * 8;
    float acc[8][4];
    #pragma unroll
    for (int r = 0; r < 8; r++)
        #pragma unroll
        for (int q = 0; q < 4; q++) acc[r][q] = 0.f;
    #pragma unroll 2
    for (int f = 0; f < 128; f++) {
        float w0 = Ws[f * 128 +      gq];
        float w1 = Ws[f * 128 + 32 + gq];
        float w2 = Ws[f * 128 + 64 + gq];
        float w3 = Ws[f * 128 + 96 + gq];
        #pragma unroll
        for (int r = 0; r < 8; r++) {
            float x = Xs[(m0 + r) * 130 + f];
            acc[r][0] += x * w0;
            acc[r][1] += x * w1;
            acc[r][2] += x * w2;
            acc[r][3] += x * w3;
        }
    }
    #pragma unroll
    for (int r = 0; r < 8; r++) {
        int n = base + m0 + r;
        #pragma unroll
        for (int q = 0; q < 4; q++) {
            int g = q * 32 + gq;
            float v = acc[r][q] * scale;
            if (Add) v += Add[(size_t)n * 128 + g];
            O[(size_t)n * 128 + g] = v;
        }
    }
}

// ---------------- species-indexed skip GEMM (same tiling) --------------------
__global__ void k_gemm_sc(const float* __restrict__ X, const float* __restrict__ w_skip,
                          float* __restrict__ Self) {
    extern __shared__ float sm[];
    float* Ws = sm;
    float* Xs = sm + 16384;
    __shared__ int lsts[64];
    int z = blockIdx.y;
    int cnt = g_cnt[z];
    int t0 = blockIdx.x * 64;
    if (t0 >= cnt) return;
    int tid = threadIdx.x;
    const float* W = w_skip + z * 16384;
    for (int i = tid; i < 16384; i += 256) Ws[i] = W[i];
    int rows = cnt - t0; if (rows > 64) rows = 64;
    const int* lst = &g_list[z * N_NODES + t0];
    if (tid < 64) lsts[tid] = (tid < rows) ? lst[tid] : 0;
    __syncthreads();
    for (int i = tid; i < 8192; i += 256) {
        int rr = i >> 7;
        Xs[rr * 130 + (i & 127)] = (rr < rows) ? X[(size_t)lsts[rr] * 128 + (i & 127)] : 0.f;
    }
    __syncthreads();
    int gq = tid & 31;
    int h  = tid >> 5;
    int m0 = h * 8;
    float acc[8][4];
    #pragma unroll
    for (int r = 0; r < 8; r++)
        #pragma unroll
        for (int q = 0; q < 4; q++) acc[r][q] = 0.f;
    #pragma unroll 2
    for (int f = 0; f < 128; f++) {
        float w0 = Ws[f * 128 +      gq];
        float w1 = Ws[f * 128 + 32 + gq];
        float w2 = Ws[f * 128 + 64 + gq];
        float w3 = Ws[f * 128 + 96 + gq];
        #pragma unroll
        for (int r = 0; r < 8; r++) {
            float x = Xs[(m0 + r) * 130 + f];
            acc[r][0] += x * w0;
            acc[r][1] += x * w1;
            acc[r][2] += x * w2;
            acc[r][3] += x * w3;
        }
    }
    #pragma unroll
    for (int r = 0; r < 8; r++) {
        int m = m0 + r;
        if (m < rows) {
            #pragma unroll
            for (int q = 0; q < 4; q++)
                Self[(size_t)lsts[m] * 128 + q * 32 + gq] = acc[r][q] * INV_SQRT1280;
        }
    }
}

// ---------------- vector-channel GEMM (g-quad, 16-row tile) ------------------
// O[n,g,c] = sum_f X[n,f,c] W[f,g]; gq = tid&31 owns 4 channels; h = tid>>5
// owns 2 rows. Per f: 4 w-LDS + 6 x-LDS + 24 FFMA.
__global__ void k_gemm_v(const float* __restrict__ X, const float* __restrict__ W,
                         float* __restrict__ O, float scale) {
    extern __shared__ float sm[];
    float* Ws = sm;           // 16384
    float* Xv = sm + 16384;   // 16*384
    int tid = threadIdx.x;
    for (int i = tid; i < 16384; i += 256) Ws[i] = W[i];
    int base = blockIdx.x * 16;
    const float* Xrow = X + (size_t)base * 384;
    for (int i = tid; i < 6144; i += 256) Xv[i] = Xrow[i];
    __syncthreads();
    int gq = tid & 31;
    int h  = tid >> 5;        // 0..7, rows [2h, 2h+2)
    float acc[2][3][4];
    #pragma unroll
    for (int r = 0; r < 2; r++)
        #pragma unroll
        for (int c = 0; c < 3; c++)
            #pragma unroll
            for (int q = 0; q < 4; q++) acc[r][c][q] = 0.f;
    #pragma unroll 2
    for (int f = 0; f < 128; f++) {
        float w0 = Ws[f * 128 +      gq];
        float w1 = Ws[f * 128 + 32 + gq];
        float w2 = Ws[f * 128 + 64 + gq];
        float w3 = Ws[f * 128 + 96 + gq];
        #pragma unroll
        for (int r = 0; r < 2; r++) {
            int bo = (h * 2 + r) * 384 + f * 3;
            float x0 = Xv[bo + 0], x1 = Xv[bo + 1], x2 = Xv[bo + 2];
            acc[r][0][0] += x0 * w0; acc[r][0][1] += x0 * w1;
            acc[r][0][2] += x0 * w2; acc[r][0][3] += x0 * w3;
            acc[r][1][0] += x1 * w0; acc[r][1][1] += x1 * w1;
            acc[r][1][2] += x1 * w2; acc[r][1][3] += x1 * w3;
            acc[r][2][0] += x2 * w0; acc[r][2][1] += x2 * w1;
            acc[r][2][2] += x2 * w2; acc[r][2][3] += x2 * w3;
        }
    }
    #pragma unroll
    for (int r = 0; r < 2; r++) {
        size_t nb = (size_t)(base + h * 2 + r) * 384;
        #pragma unroll
        for (int q = 0; q < 4; q++) {
            int g = q * 32 + gq;
            O[nb + g * 3 + 0] = acc[r][0][q] * scale;
            O[nb + g * 3 + 1] = acc[r][1][q] * scale;
            O[nb + g * 3 + 2] = acc[r][2][q] * scale;
        }
    }
}

// ---------------- radial MLP layers 1..3 (8->64->64->64, silu, f32x2) --------
__global__ void k_mlp123(const float* __restrict__ radial,
                         const float* __restrict__ w1,
                         const float* __restrict__ w2,
                         const float* __restrict__ w3) {
    __shared__ float W1s[512];
    __shared__ float W2s[4096];
    __shared__ float W3s[4096];
    int tid = threadIdx.x;
    for (int i = tid; i < 512; i += 128) W1s[i] = w1[i];
    for (int i = tid; i < 4096; i += 128) { W2s[i] = w2[i]; W3s[i] = w3[i]; }
    int e = blockIdx.x * 128 + tid;
    float r[8];
    *(float4*)&r[0] = *(const float4*)&radial[(size_t)e * 8];
    *(float4*)&r[4] = *(const float4*)&radial[(size_t)e * 8 + 4];
    __syncthreads();
    const ull* W1u = (const ull*)W1s;
    const ull* W2u = (const ull*)W2s;
    const ull* W3u = (const ull*)W3s;

    ull acc[32];
    float l[64];
    // layer 1 (8 -> 64)
    #pragma unroll
    for (int j = 0; j < 32; j++) acc[j] = 0ull;
    #pragma unroll
    for (int k = 0; k < 8; k++) {
        ull rk = pack2(r[k], r[k]);
        #pragma unroll
        for (int j = 0; j < 32; j++) fma2(acc[j], W1u[k * 32 + j], rk);
    }
    #pragma unroll
    for (int j = 0; j < 32; j++) {
        float2 v = unpack2(acc[j]);
        l[2 * j]     = silu_f(v.x * INV_SQRT8);
        l[2 * j + 1] = silu_f(v.y * INV_SQRT8);
    }
    // layer 2 (64 -> 64)
    #pragma unroll
    for (int j = 0; j < 32; j++) acc[j] = 0ull;
    #pragma unroll 4
    for (int k = 0; k < 64; k++) {
        ull lk = pack2(l[k], l[k]);
        #pragma unroll
        for (int j = 0; j < 32; j++) fma2(acc[j], W2u[k * 32 + j], lk);
    }
    #pragma unroll
    for (int j = 0; j < 32; j++) {
        float2 v = unpack2(acc[j]);
        l[2 * j]     = silu_f(v.x * 0.125f);
        l[2 * j + 1] = silu_f(v.y * 0.125f);
    }
    // layer 3 (64 -> 64) -> transposed global
    #pragma unroll
    for (int j = 0; j < 32; j++) acc[j] = 0ull;
    #pragma unroll 4
    for (int k = 0; k < 64; k++) {
        ull lk = pack2(l[k], l[k]);
        #pragma unroll
        for (int j = 0; j < 32; j++) fma2(acc[j], W3u[k * 32 + j], lk);
    }
    #pragma unroll
    for (int j = 0; j < 32; j++) {
        float2 v = unpack2(acc[j]);
        g_h3t[(size_t)(2 * j)     * E_EDGES + e] = silu_f(v.x * 0.125f);
        g_h3t[(size_t)(2 * j + 1) * E_EDGES + e] = silu_f(v.y * 0.125f);
    }
}

// ---------------- edge kernel: MLP L4 + tensor product + scatter -------------
// 512 threads = 8 groups x 64; each group handles 8 edges; 64 edges/iteration.
// h3 staged as DUPLICATED pairs (a,a): mainloop reads 1 broadcast LDS.64/edge/k
// instead of LDS + pack2. h3d stride 65 ull keeps staging STS.64 conflict-free.
__global__ void __launch_bounds__(512, 1)
k_edge(const float* __restrict__ w4,
       const float* __restrict__ vectors,
       const int* __restrict__ senders,
       const int* __restrict__ receivers) {
    extern __shared__ float sm[];
    float* W4s = sm;                               // 40960 floats (160KB)
    ull*   h3d = (ull*)(sm + 40960);               // 64 edges * 65 ull (33.3KB)
    float* Y1s = sm + 40960 + 8320;                // 64 * 4
    int*   ss  = (int*)(sm + 40960 + 8320 + 256);  // 64
    int*   rr  = ss + 64;                          // 64
    const ull* W4s2 = (const ull*)W4s;

    int t  = threadIdx.x;
    int gr = t >> 6;        // 0..7
    int c2 = t & 63;        // channel pair index

    for (int i = t; i < 40960; i += 512) W4s[i] = w4[i];
    __syncthreads();

    int ngroups = E_EDGES / 64;
    for (int gi = blockIdx.x; gi < ngroups; gi += gridDim.x) {
        int eb = gi * 64;
        __syncthreads();
        for (int i = t; i < 4096; i += 512) {
            int k = i >> 6, e = i & 63;   // lanes -> e: coalesced LDG
            float v = g_h3t[(size_t)k * E_EDGES + eb + e];
            h3d[e * 65 + k] = pack2(v, v);  // stride-65: conflict-free STS.64
        }
        if (t < 64) {
            int e = eb + t;
            ss[t] = senders[e];
            rr[t] = receivers[e];
            float vx = vectors[e * 3], vy = vectors[e * 3 + 1], vz = vectors[e * 3 + 2];
            float inv = 1.0f / (sqrtf(vx * vx + vy * vy + vz * vz) + 1e-9f);
            Y1s[t * 4 + 0] = vx * inv; Y1s[t * 4 + 1] = vy * inv; Y1s[t * 4 + 2] = vz * inv;
        }
        __syncthreads();

        ull acc[5][8];
        #pragma unroll
        for (int p = 0; p < 5; p++)
            #pragma unroll
            for (int ee = 0; ee < 8; ee++) acc[p][ee] = 0ull;

        #pragma unroll 2
        for (int k = 0; k < 64; k++) {
            ull av[8];
            #pragma unroll
            for (int ee = 0; ee < 8; ee++) av[ee] = h3d[(gr * 8 + ee) * 65 + k];
            #pragma unroll
            for (int p = 0; p < 5; p++) {
                ull w = W4s2[k * 320 + p * 64 + c2];
                #pragma unroll
                for (int ee = 0; ee < 8; ee++) fma2(acc[p][ee], w, av[ee]);
            }
        }

        #pragma unroll
        for (int ee = 0; ee < 8; ee++) {
            int le = gr * 8 + ee;
            float2 m0 = unpack2(acc[0][ee]);
            float2 m1 = unpack2(acc[1][ee]);
            float2 m2 = unpack2(acc[2][ee]);
            float2 m3 = unpack2(acc[3][ee]);
            float2 m4 = unpack2(acc[4][ee]);
            m0.x *= K_MIX; m0.y *= K_MIX; m1.x *= K_MIX; m1.y *= K_MIX;
            m2.x *= K_MIX; m2.y *= K_MIX; m3.x *= K_MIX; m3.y *= K_MIX;
            m4.x *= K_MIX; m4.y *= K_MIX;
            int s   = ss[le];
            int rcv = rr[le];
            float y0 = Y1s[le * 4 + 0], y1 = Y1s[le * 4 + 1], y2 = Y1s[le * 4 + 2];

            float2 es2 = *(const float2*)&g_hs[(size_t)s * 128 + 2 * c2];
            const float* evp = &g_hv[(size_t)s * 384 + 6 * c2];
            float2 e0 = *(const float2*)(evp + 0);
            float2 e1 = *(const float2*)(evp + 2);
            float2 e2 = *(const float2*)(evp + 4);
            // channel a vector = (e0.x, e0.y, e1.x); channel b = (e1.y, e2.x, e2.y)
            float dota = e0.x * y0 + e0.y * y1 + e1.x * y2;
            float dotb = e1.y * y0 + e2.x * y1 + e2.y * y2;

            float m0a = m0.x * es2.x + m1.x * dota * INV_SQRT3F;
            float m0b = m0.y * es2.y + m1.y * dotb * INV_SQRT3F;

            // cross(ev, Y1)
            float cax = e0.y * y2 - e1.x * y1;
            float cay = e1.x * y0 - e0.x * y2;
            float caz = e0.x * y1 - e0.y * y0;
            float cbx = e2.x * y2 - e2.y * y1;
            float cby = e2.y * y0 - e1.y * y2;
            float cbz = e1.y * y1 - e2.x * y0;

            float* as = &g_aggs[(size_t)rcv * 128 + 2 * c2];
            atomicAdd(as + 0, m0a);
            atomicAdd(as + 1, m0b);
            float* av_ = &g_aggv[(size_t)rcv * 384 + 6 * c2];
            atomicAdd(av_ + 0, m2.x * es2.x * y0 + m3.x * e0.x + m4.x * INV_SQRT2F * cax);
            atomicAdd(av_ + 1, m2.x * es2.x * y1 + m3.x * e0.y + m4.x * INV_SQRT2F * cay);
            atomicAdd(av_ + 2, m2.x * es2.x * y2 + m3.x * e1.x + m4.x * INV_SQRT2F * caz);
            atomicAdd(av_ + 3, m2.y * es2.y * y0 + m3.y * e1.y + m4.y * INV_SQRT2F * cbx);
            atomicAdd(av_ + 4, m2.y * es2.y * y1 + m3.y * e2.x + m4.y * INV_SQRT2F * cby);
            atomicAdd(av_ + 5, m2.y * es2.y * y2 + m3.y * e2.y + m4.y * INV_SQRT2F * cbz);
        }
    }
}

// ---------------- symmetric contraction features -----------------------------
__global__ void k_feats(const float* __restrict__ w_sc, const int* __restrict__ species) {
    int t = threadIdx.x;
    int n = blockIdx.x * 2 + (t >> 7);
    int f = t & 127;
    int z = species[n];
    float w0 = w_sc[z * 384 + f]        * INV_SQRT10F;
    float w1 = w_sc[z * 384 + 128 + f]  * INV_SQRT10F;
    float w2 = w_sc[z * 384 + 256 + f]  * INV_SQRT10F;
    float xs = g_xs[(size_t)n * 128 + f];
    const float* xv = &g_xv[(size_t)n * 384 + f * 3];
    float vv = xv[0] * xv[0] + xv[1] * xv[1] + xv[2] * xv[2];
    g_tmp[(size_t)n * 128 + f] = w0 * xs + w1 * xs * xs + w2 * vv;
}

// ---------------- readout ----------------------------------------------------
__global__ void k_read(const float* __restrict__ feats,
                       const float* __restrict__ w_read1,
                       const float* __restrict__ w_read2,
                       float* __restrict__ out) {
    __shared__ float w1s[2048];
    __shared__ float fs[16 * 132];
    int t = threadIdx.x;
    int nb = blockIdx.x * 16;
    for (int i = t; i < 2048; i += 256) w1s[i] = w_read1[i];
    for (int i = t; i < 2048; i += 256) {
        int node = i >> 7, c = i & 127;
        fs[node * 132 + c] = feats[(size_t)(nb + node) * 128 + c];
    }
    __syncthreads();
    int r = t >> 4, j = t & 15;
    float acc = 0.f;
    #pragma unroll 4
    for (int f = 0; f < 128; f++) acc += fs[r * 132 + f] * w1s[f * 16 + j];
    float a = silu_f(acc * INV_SQRT128) * w_read2[j] * 0.25f;
    #pragma unroll
    for (int m = 8; m; m >>= 1) a += __shfl_xor_sync(0xffffffffu, a, m);
    if (j == 0) out[nb + r] = a;
}

// ---------------- launch -----------------------------------------------------
extern "C" void kernel_launch(void* const* d_in, const int* in_sizes, int n_in,
                              void* d_out, int out_size) {
    const float* vectors      = (const float*)d_in[0];
    const float* node_scalars = (const float*)d_in[1];
    const float* node_vectors = (const float*)d_in[2];
    const float* radial       = (const float*)d_in[3];
    const float* w_skip       = (const float*)d_in[4];
    const float* w_up0        = (const float*)d_in[5];
    const float* w_up1        = (const float*)d_in[6];
    const float* mlp_w1       = (const float*)d_in[7];
    const float* mlp_w2       = (const float*)d_in[8];
    const float* mlp_w3       = (const float*)d_in[9];
    const float* mlp_w4       = (const float*)d_in[10];
    const float* w_down0      = (const float*)d_in[11];
    const float* w_down1      = (const float*)d_in[12];
    const float* w_sc         = (const float*)d_in[13];
    const float* w_post       = (const float*)d_in[14];
    const float* w_read1      = (const float*)d_in[15];
    const float* w_read2      = (const float*)d_in[16];
    const int*   senders      = (const int*)d_in[17];
    const int*   receivers    = (const int*)d_in[18];
    const int*   species      = (const int*)d_in[19];

    float* out   = (float*)d_out;            // [N] energies
    float* feats = (float*)d_out + N_NODES;  // [N,128] feats

    float *hs, *hv, *selfc, *aggs, *aggv, *xs, *xv, *tmp;
    int   *cnt;
    cudaGetSymbolAddress((void**)&hs,    g_hs);
    cudaGetSymbolAddress((void**)&hv,    g_hv);
    cudaGetSymbolAddress((void**)&selfc, g_self);
    cudaGetSymbolAddress((void**)&aggs,  g_aggs);
    cudaGetSymbolAddress((void**)&aggv,  g_aggv);
    cudaGetSymbolAddress((void**)&xs,    g_xs);
    cudaGetSymbolAddress((void**)&xv,    g_xv);
    cudaGetSymbolAddress((void**)&tmp,   g_tmp);
    cudaGetSymbolAddress((void**)&cnt,   g_cnt);

    const int SM_GEMM_S = (16384 + 64 * 130) * 4;
    const int SM_GEMM_V = (16384 + 6144) * 4;
    const int SM_EDGE   = (40960 + 8320 + 256 + 128) * 4;  // ~195KB

    cudaFuncSetAttribute(k_gemm_s,  cudaFuncAttributeMaxDynamicSharedMemorySize, SM_GEMM_S);
    cudaFuncSetAttribute(k_gemm_sc, cudaFuncAttributeMaxDynamicSharedMemorySize, SM_GEMM_S);
    cudaFuncSetAttribute(k_gemm_v,  cudaFuncAttributeMaxDynamicSharedMemorySize, SM_GEMM_V);
    cudaFuncSetAttribute(k_edge,    cudaFuncAttributeMaxDynamicSharedMemorySize, SM_EDGE);

    cudaMemsetAsync(aggs, 0, (size_t)N_NODES * F_CH * 4);
    cudaMemsetAsync(aggv, 0, (size_t)N_NODES * F_CH * 12);
    cudaMemsetAsync(cnt,  0, Z_SP * 4);

    k_species_list<<<N_NODES / 256, 256>>>(species);
    k_gemm_sc<<<dim3(512, Z_SP), 256, SM_GEMM_S>>>(node_scalars, w_skip, selfc);
    k_gemm_s<<<512, 256, SM_GEMM_S>>>(node_scalars, w_up0, hs, (const float*)0, INV_SQRT128);
    k_gemm_v<<<N_NODES / 16, 256, SM_GEMM_V>>>(node_vectors, w_up1, hv, INV_SQRT128);
    k_mlp123<<<E_EDGES / 128, 128>>>(radial, mlp_w1, mlp_w2, mlp_w3);
    k_edge<<<148, 512, SM_EDGE>>>(mlp_w4, vectors, senders, receivers);
    k_gemm_s<<<512, 256, SM_GEMM_S>>>(aggs, w_down0, xs, (const float*)0, INV_SQRT128);
    k_gemm_v<<<N_NODES / 16, 256, SM_GEMM_V>>>(aggv, w_down1, xv, INV_SQRT128);
    k_feats<<<N_NODES / 2, 256>>>(w_sc, species);
    k_gemm_s<<<512, 256, SM_GEMM_S>>>(tmp, w_post, feats, selfc, INV_SQRT128);
    k_read<<<N_NODES / 16, 256>>>(feats, w_read1, w_read2, out);
}

// round 17
// speedup vs baseline: 1.5923x; 1.0078x over previous
#include <cuda_runtime.h>
#include <math.h>

#define N_NODES 32768
#define E_EDGES 524288
#define F_CH    128
#define Z_SP    10

typedef unsigned long long ull;

// ---------------- scratch (static device globals; no allocation) -------------
__device__ float g_hs  [N_NODES * F_CH];
__device__ float g_hv  [N_NODES * F_CH * 3];
__device__ float g_self[N_NODES * F_CH];
__device__ float g_h3t [64 * E_EDGES];        // transposed [k][e]
__device__ float g_aggs[N_NODES * F_CH];
__device__ float g_aggv[N_NODES * F_CH * 3];
__device__ float g_xs  [N_NODES * F_CH];
__device__ float g_xv  [N_NODES * F_CH * 3];
__device__ float g_tmp [N_NODES * F_CH];
__device__ int   g_cnt [Z_SP];
__device__ int   g_list[Z_SP * N_NODES];

#define INV_SQRT128  0.08838834764831845f
#define INV_SQRT1280 0.027950849718747372f
#define INV_SQRT8    0.35355339059327373f
#define INV_SQRT3F   0.5773502691896258f
#define INV_SQRT2F   0.7071067811865476f
#define INV_SQRT10F  0.31622776601683794f
#define K_MIX        0.015625f   /* inv(w4)=1/8 times EPS=1/8 */

__device__ __forceinline__ float silu_f(float x) {
    return x * (1.0f / (1.0f + __expf(-x)));
}
__device__ __forceinline__ ull pack2(float x, float y) {
    ull r; asm("mov.b64 %0, {%1, %2};" : "=l"(r) : "f"(x), "f"(y)); return r;
}
__device__ __forceinline__ float2 unpack2(ull v) {
    float2 r; asm("mov.b64 {%0, %1}, %2;" : "=f"(r.x), "=f"(r.y) : "l"(v)); return r;
}
__device__ __forceinline__ void fma2(ull &d, ull a, ull b) {
    asm("fma.rn.f32x2 %0, %1, %2, %0;" : "+l"(d) : "l"(a), "l"(b));
}

// ---------------- species bucketing ------------------------------------------
__global__ void k_species_list(const int* __restrict__ species) {
    int n = blockIdx.x * 256 + threadIdx.x;
    if (n < N_NODES) {
        int z = species[n];
        int pos = atomicAdd(&g_cnt[z], 1);
        g_list[z * N_NODES + pos] = n;
    }
}

// ---------------- scalar-channel GEMM [64-row tile,128]@[128,128] ------------
// 256 thr: gq = tid&31 owns channels {gq,32+gq,64+gq,96+gq}; h = tid>>5 owns
// 8 rows. Per f: 4 w-LDS (coalesced) + 8 x-LDS (broadcast) + 32 FFMA.
__global__ void k_gemm_s(const float* __restrict__ X, const float* __restrict__ W,
                         float* __restrict__ O, const float* __restrict__ Add,
                         float scale) {
    extern __shared__ float sm[];
    float* Ws = sm;           // 128*128
    float* Xs = sm + 16384;   // 64 rows * 130 stride
    int tid = threadIdx.x;
    for (int i = tid; i < 16384; i += 256) Ws[i] = W[i];
    int base = blockIdx.x * 64;
    const float* Xrow = X + (size_t)base * 128;
    for (int i = tid; i < 8192; i += 256) Xs[(i >> 7) * 130 + (i & 127)] = Xrow[i];
    __syncthreads();
    int gq = tid & 31;
    int h  = tid >> 5;        // 0..7, rows [8h, 8h+8)
    int m0 = h * 8;
    float acc[8][4];
    #pragma unroll
    for (int r = 0; r < 8; r++)
        #pragma unroll
        for (int q = 0; q < 4; q++) acc[r][q] = 0.f;
    #pragma unroll 2
    for (int f = 0; f < 128; f++) {
        float w0 = Ws[f * 128 +      gq];
        float w1 = Ws[f * 128 + 32 + gq];
        float w2 = Ws[f * 128 + 64 + gq];
        float w3 = Ws[f * 128 + 96 + gq];
        #pragma unroll
        for (int r = 0; r < 8; r++) {
            float x = Xs[(m0 + r) * 130 + f];
            acc[r][0] += x * w0;
            acc[r][1] += x * w1;
            acc[r][2] += x * w2;
            acc[r][3] += x * w3;
        }
    }
    #pragma unroll
    for (int r = 0; r < 8; r++) {
        int n = base + m0 + r;
        #pragma unroll
        for (int q = 0; q < 4; q++) {
            int g = q * 32 + gq;
            float v = acc[r][q] * scale;
            if (Add) v += Add[(size_t)n * 128 + g];
            O[(size_t)n * 128 + g] = v;
        }
    }
}

// ---------------- species-indexed skip GEMM (same tiling) --------------------
__global__ void k_gemm_sc(const float* __restrict__ X, const float* __restrict__ w_skip,
                          float* __restrict__ Self) {
    extern __shared__ float sm[];
    float* Ws = sm;
    float* Xs = sm + 16384;
    __shared__ int lsts[64];
    int z = blockIdx.y;
    int cnt = g_cnt[z];
    int t0 = blockIdx.x * 64;
    if (t0 >= cnt) return;
    int tid = threadIdx.x;
    const float* W = w_skip + z * 16384;
    for (int i = tid; i < 16384; i += 256) Ws[i] = W[i];
    int rows = cnt - t0; if (rows > 64) rows = 64;
    const int* lst = &g_list[z * N_NODES + t0];
    if (tid < 64) lsts[tid] = (tid < rows) ? lst[tid] : 0;
    __syncthreads();
    for (int i = tid; i < 8192; i += 256) {
        int rr = i >> 7;
        Xs[rr * 130 + (i & 127)] = (rr < rows) ? X[(size_t)lsts[rr] * 128 + (i & 127)] : 0.f;
    }
    __syncthreads();
    int gq = tid & 31;
    int h  = tid >> 5;
    int m0 = h * 8;
    float acc[8][4];
    #pragma unroll
    for (int r = 0; r < 8; r++)
        #pragma unroll
        for (int q = 0; q < 4; q++) acc[r][q] = 0.f;
    #pragma unroll 2
    for (int f = 0; f < 128; f++) {
        float w0 = Ws[f * 128 +      gq];
        float w1 = Ws[f * 128 + 32 + gq];
        float w2 = Ws[f * 128 + 64 + gq];
        float w3 = Ws[f * 128 + 96 + gq];
        #pragma unroll
        for (int r = 0; r < 8; r++) {
            float x = Xs[(m0 + r) * 130 + f];
            acc[r][0] += x * w0;
            acc[r][1] += x * w1;
            acc[r][2] += x * w2;
            acc[r][3] += x * w3;
        }
    }
    #pragma unroll
    for (int r = 0; r < 8; r++) {
        int m = m0 + r;
        if (m < rows) {
            #pragma unroll
            for (int q = 0; q < 4; q++)
                Self[(size_t)lsts[m] * 128 + q * 32 + gq] = acc[r][q] * INV_SQRT1280;
        }
    }
}

// ---------------- vector-channel GEMM (g-quad, 16-row tile) ------------------
__global__ void k_gemm_v(const float* __restrict__ X, const float* __restrict__ W,
                         float* __restrict__ O, float scale) {
    extern __shared__ float sm[];
    float* Ws = sm;           // 16384
    float* Xv = sm + 16384;   // 16*384
    int tid = threadIdx.x;
    for (int i = tid; i < 16384; i += 256) Ws[i] = W[i];
    int base = blockIdx.x * 16;
    const float* Xrow = X + (size_t)base * 384;
    for (int i = tid; i < 6144; i += 256) Xv[i] = Xrow[i];
    __syncthreads();
    int gq = tid & 31;
    int h  = tid >> 5;        // 0..7, rows [2h, 2h+2)
    float acc[2][3][4];
    #pragma unroll
    for (int r = 0; r < 2; r++)
        #pragma unroll
        for (int c = 0; c < 3; c++)
            #pragma unroll
            for (int q = 0; q < 4; q++) acc[r][c][q] = 0.f;
    #pragma unroll 2
    for (int f = 0; f < 128; f++) {
        float w0 = Ws[f * 128 +      gq];
        float w1 = Ws[f * 128 + 32 + gq];
        float w2 = Ws[f * 128 + 64 + gq];
        float w3 = Ws[f * 128 + 96 + gq];
        #pragma unroll
        for (int r = 0; r < 2; r++) {
            int bo = (h * 2 + r) * 384 + f * 3;
            float x0 = Xv[bo + 0], x1 = Xv[bo + 1], x2 = Xv[bo + 2];
            acc[r][0][0] += x0 * w0; acc[r][0][1] += x0 * w1;
            acc[r][0][2] += x0 * w2; acc[r][0][3] += x0 * w3;
            acc[r][1][0] += x1 * w0; acc[r][1][1] += x1 * w1;
            acc[r][1][2] += x1 * w2; acc[r][1][3] += x1 * w3;
            acc[r][2][0] += x2 * w0; acc[r][2][1] += x2 * w1;
            acc[r][2][2] += x2 * w2; acc[r][2][3] += x2 * w3;
        }
    }
    #pragma unroll
    for (int r = 0; r < 2; r++) {
        size_t nb = (size_t)(base + h * 2 + r) * 384;
        #pragma unroll
        for (int q = 0; q < 4; q++) {
            int g = q * 32 + gq;
            O[nb + g * 3 + 0] = acc[r][0][q] * scale;
            O[nb + g * 3 + 1] = acc[r][1][q] * scale;
            O[nb + g * 3 + 2] = acc[r][2][q] * scale;
        }
    }
}

// ---------------- radial MLP layers 1..3 (8->64->64->64, silu, f32x2) --------
__global__ void k_mlp123(const float* __restrict__ radial,
                         const float* __restrict__ w1,
                         const float* __restrict__ w2,
                         const float* __restrict__ w3) {
    __shared__ float W1s[512];
    __shared__ float W2s[4096];
    __shared__ float W3s[4096];
    int tid = threadIdx.x;
    for (int i = tid; i < 512; i += 128) W1s[i] = w1[i];
    for (int i = tid; i < 4096; i += 128) { W2s[i] = w2[i]; W3s[i] = w3[i]; }
    int e = blockIdx.x * 128 + tid;
    float r[8];
    *(float4*)&r[0] = *(const float4*)&radial[(size_t)e * 8];
    *(float4*)&r[4] = *(const float4*)&radial[(size_t)e * 8 + 4];
    __syncthreads();
    const ull* W1u = (const ull*)W1s;
    const ull* W2u = (const ull*)W2s;
    const ull* W3u = (const ull*)W3s;

    ull acc[32];
    float l[64];
    // layer 1 (8 -> 64)
    #pragma unroll
    for (int j = 0; j < 32; j++) acc[j] = 0ull;
    #pragma unroll
    for (int k = 0; k < 8; k++) {
        ull rk = pack2(r[k], r[k]);
        #pragma unroll
        for (int j = 0; j < 32; j++) fma2(acc[j], W1u[k * 32 + j], rk);
    }
    #pragma unroll
    for (int j = 0; j < 32; j++) {
        float2 v = unpack2(acc[j]);
        l[2 * j]     = silu_f(v.x * INV_SQRT8);
        l[2 * j + 1] = silu_f(v.y * INV_SQRT8);
    }
    // layer 2 (64 -> 64)
    #pragma unroll
    for (int j = 0; j < 32; j++) acc[j] = 0ull;
    #pragma unroll 4
    for (int k = 0; k < 64; k++) {
        ull lk = pack2(l[k], l[k]);
        #pragma unroll
        for (int j = 0; j < 32; j++) fma2(acc[j], W2u[k * 32 + j], lk);
    }
    #pragma unroll
    for (int j = 0; j < 32; j++) {
        float2 v = unpack2(acc[j]);
        l[2 * j]     = silu_f(v.x * 0.125f);
        l[2 * j + 1] = silu_f(v.y * 0.125f);
    }
    // layer 3 (64 -> 64) -> transposed global
    #pragma unroll
    for (int j = 0; j < 32; j++) acc[j] = 0ull;
    #pragma unroll 4
    for (int k = 0; k < 64; k++) {
        ull lk = pack2(l[k], l[k]);
        #pragma unroll
        for (int j = 0; j < 32; j++) fma2(acc[j], W3u[k * 32 + j], lk);
    }
    #pragma unroll
    for (int j = 0; j < 32; j++) {
        float2 v = unpack2(acc[j]);
        g_h3t[(size_t)(2 * j)     * E_EDGES + e] = silu_f(v.x * 0.125f);
        g_h3t[(size_t)(2 * j + 1) * E_EDGES + e] = silu_f(v.y * 0.125f);
    }
}

// ---------------- edge kernel: MLP L4 + tensor product + scatter -------------
// 512 threads = 8 groups x 64; each group handles 8 edges; 64 edges/iteration.
__global__ void __launch_bounds__(512, 1)
k_edge(const float* __restrict__ w4,
       const float* __restrict__ vectors,
       const int* __restrict__ senders,
       const int* __restrict__ receivers) {
    extern __shared__ float sm[];
    float* W4s = sm;                               // 40960 floats (160KB)
    ull*   h3d = (ull*)(sm + 40960);               // 64 edges * 65 ull (33.3KB)
    float* Y1s = sm + 40960 + 8320;                // 64 * 4
    int*   ss  = (int*)(sm + 40960 + 8320 + 256);  // 64
    int*   rr  = ss + 64;                          // 64
    const ull* W4s2 = (const ull*)W4s;

    int t  = threadIdx.x;
    int gr = t >> 6;        // 0..7
    int c2 = t & 63;        // channel pair index

    for (int i = t; i < 40960; i += 512) W4s[i] = w4[i];
    __syncthreads();

    int ngroups = E_EDGES / 64;
    for (int gi = blockIdx.x; gi < ngroups; gi += gridDim.x) {
        int eb = gi * 64;
        __syncthreads();
        for (int i = t; i < 4096; i += 512) {
            int k = i >> 6, e = i & 63;   // lanes -> e: coalesced LDG
            float v = g_h3t[(size_t)k * E_EDGES + eb + e];
            h3d[e * 65 + k] = pack2(v, v);  // stride-65: conflict-free STS.64
        }
        if (t < 64) {
            int e = eb + t;
            ss[t] = senders[e];
            rr[t] = receivers[e];
            float vx = vectors[e * 3], vy = vectors[e * 3 + 1], vz = vectors[e * 3 + 2];
            float inv = 1.0f / (sqrtf(vx * vx + vy * vy + vz * vz) + 1e-9f);
            Y1s[t * 4 + 0] = vx * inv; Y1s[t * 4 + 1] = vy * inv; Y1s[t * 4 + 2] = vz * inv;
        }
        __syncthreads();

        ull acc[5][8];
        #pragma unroll
        for (int p = 0; p < 5; p++)
            #pragma unroll
            for (int ee = 0; ee < 8; ee++) acc[p][ee] = 0ull;

        #pragma unroll 2
        for (int k = 0; k < 64; k++) {
            ull av[8];
            #pragma unroll
            for (int ee = 0; ee < 8; ee++) av[ee] = h3d[(gr * 8 + ee) * 65 + k];
            #pragma unroll
            for (int p = 0; p < 5; p++) {
                ull w = W4s2[k * 320 + p * 64 + c2];
                #pragma unroll
                for (int ee = 0; ee < 8; ee++) fma2(acc[p][ee], w, av[ee]);
            }
        }

        #pragma unroll
        for (int ee = 0; ee < 8; ee++) {
            int le = gr * 8 + ee;
            float2 m0 = unpack2(acc[0][ee]);
            float2 m1 = unpack2(acc[1][ee]);
            float2 m2 = unpack2(acc[2][ee]);
            float2 m3 = unpack2(acc[3][ee]);
            float2 m4 = unpack2(acc[4][ee]);
            m0.x *= K_MIX; m0.y *= K_MIX; m1.x *= K_MIX; m1.y *= K_MIX;
            m2.x *= K_MIX; m2.y *= K_MIX; m3.x *= K_MIX; m3.y *= K_MIX;
            m4.x *= K_MIX; m4.y *= K_MIX;
            int s   = ss[le];
            int rcv = rr[le];
            float y0 = Y1s[le * 4 + 0], y1 = Y1s[le * 4 + 1], y2 = Y1s[le * 4 + 2];

            float2 es2 = *(const float2*)&g_hs[(size_t)s * 128 + 2 * c2];
            const float* evp = &g_hv[(size_t)s * 384 + 6 * c2];
            float2 e0 = *(const float2*)(evp + 0);
            float2 e1 = *(const float2*)(evp + 2);
            float2 e2 = *(const float2*)(evp + 4);
            // channel a vector = (e0.x, e0.y, e1.x); channel b = (e1.y, e2.x, e2.y)
            float dota = e0.x * y0 + e0.y * y1 + e1.x * y2;
            float dotb = e1.y * y0 + e2.x * y1 + e2.y * y2;

            float m0a = m0.x * es2.x + m1.x * dota * INV_SQRT3F;
            float m0b = m0.y * es2.y + m1.y * dotb * INV_SQRT3F;

            // cross(ev, Y1)
            float cax = e0.y * y2 - e1.x * y1;
            float cay = e1.x * y0 - e0.x * y2;
            float caz = e0.x * y1 - e0.y * y0;
            float cbx = e2.x * y2 - e2.y * y1;
            float cby = e2.y * y0 - e1.y * y2;
            float cbz = e1.y * y1 - e2.x * y0;

            float* as = &g_aggs[(size_t)rcv * 128 + 2 * c2];
            atomicAdd(as + 0, m0a);
            atomicAdd(as + 1, m0b);
            float* av_ = &g_aggv[(size_t)rcv * 384 + 6 * c2];
            atomicAdd(av_ + 0, m2.x * es2.x * y0 + m3.x * e0.x + m4.x * INV_SQRT2F * cax);
            atomicAdd(av_ + 1, m2.x * es2.x * y1 + m3.x * e0.y + m4.x * INV_SQRT2F * cay);
            atomicAdd(av_ + 2, m2.x * es2.x * y2 + m3.x * e1.x + m4.x * INV_SQRT2F * caz);
            atomicAdd(av_ + 3, m2.y * es2.y * y0 + m3.y * e1.y + m4.y * INV_SQRT2F * cbx);
            atomicAdd(av_ + 4, m2.y * es2.y * y1 + m3.y * e2.x + m4.y * INV_SQRT2F * cby);
            atomicAdd(av_ + 5, m2.y * es2.y * y2 + m3.y * e2.y + m4.y * INV_SQRT2F * cbz);
        }
    }
}

// ---------------- symmetric contraction features -----------------------------
__global__ void k_feats(const float* __restrict__ w_sc, const int* __restrict__ species) {
    int t = threadIdx.x;
    int n = blockIdx.x * 2 + (t >> 7);
    int f = t & 127;
    int z = species[n];
    float w0 = w_sc[z * 384 + f]        * INV_SQRT10F;
    float w1 = w_sc[z * 384 + 128 + f]  * INV_SQRT10F;
    float w2 = w_sc[z * 384 + 256 + f]  * INV_SQRT10F;
    float xs = g_xs[(size_t)n * 128 + f];
    const float* xv = &g_xv[(size_t)n * 384 + f * 3];
    float vv = xv[0] * xv[0] + xv[1] * xv[1] + xv[2] * xv[2];
    g_tmp[(size_t)n * 128 + f] = w0 * xs + w1 * xs * xs + w2 * vv;
}

// ---------------- readout ----------------------------------------------------
__global__ void k_read(const float* __restrict__ feats,
                       const float* __restrict__ w_read1,
                       const float* __restrict__ w_read2,
                       float* __restrict__ out) {
    __shared__ float w1s[2048];
    __shared__ float fs[16 * 132];
    int t = threadIdx.x;
    int nb = blockIdx.x * 16;
    for (int i = t; i < 2048; i += 256) w1s[i] = w_read1[i];
    for (int i = t; i < 2048; i += 256) {
        int node = i >> 7, c = i & 127;
        fs[node * 132 + c] = feats[(size_t)(nb + node) * 128 + c];
    }
    __syncthreads();
    int r = t >> 4, j = t & 15;
    float acc = 0.f;
    #pragma unroll 4
    for (int f = 0; f < 128; f++) acc += fs[r * 132 + f] * w1s[f * 16 + j];
    float a = silu_f(acc * INV_SQRT128) * w_read2[j] * 0.25f;
    #pragma unroll
    for (int m = 8; m; m >>= 1) a += __shfl_xor_sync(0xffffffffu, a, m);
    if (j == 0) out[nb + r] = a;
}

// ---------------- launch -----------------------------------------------------
extern "C" void kernel_launch(void* const* d_in, const int* in_sizes, int n_in,
                              void* d_out, int out_size) {
    const float* vectors      = (const float*)d_in[0];
    const float* node_scalars = (const float*)d_in[1];
    const float* node_vectors = (const float*)d_in[2];
    const float* radial       = (const float*)d_in[3];
    const float* w_skip       = (const float*)d_in[4];
    const float* w_up0        = (const float*)d_in[5];
    const float* w_up1        = (const float*)d_in[6];
    const float* mlp_w1       = (const float*)d_in[7];
    const float* mlp_w2       = (const float*)d_in[8];
    const float* mlp_w3       = (const float*)d_in[9];
    const float* mlp_w4       = (const float*)d_in[10];
    const float* w_down0      = (const float*)d_in[11];
    const float* w_down1      = (const float*)d_in[12];
    const float* w_sc         = (const float*)d_in[13];
    const float* w_post       = (const float*)d_in[14];
    const float* w_read1      = (const float*)d_in[15];
    const float* w_read2      = (const float*)d_in[16];
    const int*   senders      = (const int*)d_in[17];
    const int*   receivers    = (const int*)d_in[18];
    const int*   species      = (const int*)d_in[19];

    float* out   = (float*)d_out;            // [N] energies
    float* feats = (float*)d_out + N_NODES;  // [N,128] feats

    float *hs, *hv, *selfc, *aggs, *aggv, *xs, *xv, *tmp;
    int   *cnt;
    cudaGetSymbolAddress((void**)&hs,    g_hs);
    cudaGetSymbolAddress((void**)&hv,    g_hv);
    cudaGetSymbolAddress((void**)&selfc, g_self);
    cudaGetSymbolAddress((void**)&aggs,  g_aggs);
    cudaGetSymbolAddress((void**)&aggv,  g_aggv);
    cudaGetSymbolAddress((void**)&xs,    g_xs);
    cudaGetSymbolAddress((void**)&xv,    g_xv);
    cudaGetSymbolAddress((void**)&tmp,   g_tmp);
    cudaGetSymbolAddress((void**)&cnt,   g_cnt);

    const int SM_GEMM_S = (16384 + 64 * 130) * 4;
    const int SM_GEMM_V = (16384 + 6144) * 4;
    const int SM_EDGE   = (40960 + 8320 + 256 + 128) * 4;  // ~195KB

    cudaFuncSetAttribute(k_gemm_s,  cudaFuncAttributeMaxDynamicSharedMemorySize, SM_GEMM_S);
    cudaFuncSetAttribute(k_gemm_sc, cudaFuncAttributeMaxDynamicSharedMemorySize, SM_GEMM_S);
    cudaFuncSetAttribute(k_gemm_v,  cudaFuncAttributeMaxDynamicSharedMemorySize, SM_GEMM_V);
    cudaFuncSetAttribute(k_edge,    cudaFuncAttributeMaxDynamicSharedMemorySize, SM_EDGE);

    // REORDERED so k_edge lands in ncu's capture slot (-s 5 -c 1):
    // profileable launches: memset(aggs)=1, memset(aggv)=2, gemm_s=3, gemm_v=4,
    // mlp123=5, k_edge=6 <- captured. The tiny 40B memset doesn't register.
    // species_list / gemm_sc moved after edge (their only consumer is the
    // final gemm_s(post) via g_self; edge doesn't touch them).
    cudaMemsetAsync(aggs, 0, (size_t)N_NODES * F_CH * 4);
    cudaMemsetAsync(aggv, 0, (size_t)N_NODES * F_CH * 12);
    cudaMemsetAsync(cnt,  0, Z_SP * 4);

    k_gemm_s<<<512, 256, SM_GEMM_S>>>(node_scalars, w_up0, hs, (const float*)0, INV_SQRT128);
    k_gemm_v<<<N_NODES / 16, 256, SM_GEMM_V>>>(node_vectors, w_up1, hv, INV_SQRT128);
    k_mlp123<<<E_EDGES / 128, 128>>>(radial, mlp_w1, mlp_w2, mlp_w3);
    k_edge<<<148, 512, SM_EDGE>>>(mlp_w4, vectors, senders, receivers);
    k_species_list<<<N_NODES / 256, 256>>>(species);
    k_gemm_sc<<<dim3(512, Z_SP), 256, SM_GEMM_S>>>(node_scalars, w_skip, selfc);
    k_gemm_s<<<512, 256, SM_GEMM_S>>>(aggs, w_down0, xs, (const float*)0, INV_SQRT128);
    k_gemm_v<<<N_NODES / 16, 256, SM_GEMM_V>>>(aggv, w_down1, xv, INV_SQRT128);
    k_feats<<<N_NODES / 2, 256>>>(w_sc, species);
    k_gemm_s<<<512, 256, SM_GEMM_S>>>(tmp, w_post, feats, selfc, INV_SQRT128);
    k_read<<<N_NODES / 16, 256>>>(feats, w_read1, w_read2, out);
}